// round 2
// baseline (speedup 1.0000x reference)
#include <cuda_runtime.h>
#include <cstdint>

// Problem constants (fixed by the dataset)
#define NTOT 131072
#define NB   2048
#define NF   200
#define KDIM 600      // [q(200) | r(200) | h(200)]
#define GDIM 800      // 4 gates * F
#define STEPS 3

// ---------------- scratch (device globals: no cudaMalloc allowed) ----------
__device__ float g_Z[NB * KDIM];      // A matrix for GEMM: [q | r | h]
__device__ float g_C[NB * NF];        // LSTM cell state
__device__ float g_G[NB * GDIM];      // gates
__device__ float g_W[GDIM * KDIM];    // Wcat = [W_ih | W_hh], row-major [800,600]
__device__ float g_bias[GDIM];        // b_ih + b_hh
__device__ int   g_seg[NB + 2];       // segment boundaries (batch is sorted)
__device__ float g_e[NTOT];           // overflow e-buffer (long segments)

// ---------------- helpers ---------------------------------------------------
__device__ __forceinline__ uint32_t f2tf32(float f) {
    uint32_t u;
    asm("cvt.rna.tf32.f32 %0, %1;" : "=r"(u) : "f"(f));
    return u;
}

// hi/lo split for 3xTF32: a ~= hi + lo with both representable in tf32
__device__ __forceinline__ void split_tf32(float v, uint32_t& hi, uint32_t& lo) {
    hi = f2tf32(v);
    float fhi = __uint_as_float(hi & 0xffffe000u);  // tf32 value as fp32
    lo = f2tf32(v - fhi);
}

__device__ __forceinline__ void mma_tf32(float d[4], const uint32_t a[4], const uint32_t b[2]) {
    asm volatile(
        "mma.sync.aligned.m16n8k8.row.col.f32.tf32.tf32.f32 "
        "{%0,%1,%2,%3}, {%4,%5,%6,%7}, {%8,%9}, {%0,%1,%2,%3};\n"
        : "+f"(d[0]), "+f"(d[1]), "+f"(d[2]), "+f"(d[3])
        : "r"(a[0]), "r"(a[1]), "r"(a[2]), "r"(a[3]), "r"(b[0]), "r"(b[1]));
}

__device__ __forceinline__ float sigmoidf_(float x) { return 1.0f / (1.0f + expf(-x)); }

// ---------------- prep: Wcat + bias ----------------------------------------
__global__ void k_prep(const float* __restrict__ W_ih, const float* __restrict__ W_hh,
                       const float* __restrict__ b_ih, const float* __restrict__ b_hh) {
    int idx = blockIdx.x * blockDim.x + threadIdx.x;
    const int WTOT = GDIM * KDIM;
    if (idx < WTOT) {
        int j = idx / KDIM, k = idx % KDIM;
        g_W[idx] = (k < 400) ? W_ih[j * 400 + k] : W_hh[j * 200 + (k - 400)];
    } else if (idx < WTOT + GDIM) {
        int j = idx - WTOT;
        g_bias[j] = b_ih[j] + b_hh[j];
    }
}

// ---------------- segment boundaries (batch sorted) -------------------------
__global__ void k_bounds(const int* __restrict__ batch, int n) {
    int i = blockIdx.x * blockDim.x + threadIdx.x;
    if (i >= n) return;
    int b = batch[i];
    if (i == 0) {
        for (int q = 0; q <= b; ++q) g_seg[q] = 0;
    } else {
        int pb = batch[i - 1];
        for (int q = pb + 1; q <= b; ++q) g_seg[q] = i;
    }
    if (i == n - 1) {
        for (int q = b + 1; q <= NB; ++q) g_seg[q] = n;
    }
}

// ---------------- Z init: Z[:,0:400] = q_star_in, C = 0 ---------------------
__global__ void k_zinit(const float* __restrict__ qstar) {
    int idx = blockIdx.x * blockDim.x + threadIdx.x;
    if (idx >= NB * KDIM) return;
    int b = idx / KDIM, u = idx % KDIM;
    if (u < 400) g_Z[idx] = qstar[b * 400 + u];
    else         g_C[b * NF + (u - 400)] = 0.0f;
}

// ---------------- h0 = segment_sum(cos * x) → Z[:,400:600] ------------------
__global__ void __launch_bounds__(256) k_h0(const float* __restrict__ x,
                                            const float* __restrict__ cosc) {
    __shared__ float part[8][NF];
    int b = blockIdx.x;
    int s0 = g_seg[b], s1 = g_seg[b + 1];
    int tid = threadIdx.x, lane = tid & 31, wid = tid >> 5;

    float4 aA = make_float4(0.f, 0.f, 0.f, 0.f);
    float4 aB = make_float4(0.f, 0.f, 0.f, 0.f);
    for (int n = s0 + wid; n < s1; n += 8) {
        float c = __ldg(cosc + n);
        const float4* row = (const float4*)(x + (size_t)n * NF);
        float4 v = row[lane];
        aA.x += c * v.x; aA.y += c * v.y; aA.z += c * v.z; aA.w += c * v.w;
        if (lane < 18) {
            float4 v2 = row[32 + lane];
            aB.x += c * v2.x; aB.y += c * v2.y; aB.z += c * v2.z; aB.w += c * v2.w;
        }
    }
    part[wid][4 * lane + 0] = aA.x; part[wid][4 * lane + 1] = aA.y;
    part[wid][4 * lane + 2] = aA.z; part[wid][4 * lane + 3] = aA.w;
    if (lane < 18) {
        part[wid][128 + 4 * lane + 0] = aB.x; part[wid][128 + 4 * lane + 1] = aB.y;
        part[wid][128 + 4 * lane + 2] = aB.z; part[wid][128 + 4 * lane + 3] = aB.w;
    }
    __syncthreads();
    if (tid < NF) {
        float s = 0.f;
#pragma unroll
        for (int w = 0; w < 8; ++w) s += part[w][tid];
        g_Z[b * KDIM + 400 + tid] = s;
    }
}

// -------- 3xTF32 GEMM: G = Z[2048,600] @ Wcat[800,600]^T (fp32-accurate) ----
#define BM 128
#define BN 80
#define BK 8
#define KCH (KDIM / BK)   // 75

__global__ void __launch_bounds__(256) k_gemm() {
    // hi/lo pairs, double buffered; stride 12 to dodge bank conflicts
    __shared__ uint32_t AsH[2][BM * 12];
    __shared__ uint32_t AsL[2][BM * 12];
    __shared__ uint32_t BsH[2][BN * 12];
    __shared__ uint32_t BsL[2][BN * 12];

    const float* Z = g_Z;
    const float* W = g_W;
    float* G = g_G;

    int m0 = blockIdx.x * BM, n0 = blockIdx.y * BN;
    int tid = threadIdx.x, lane = tid & 31, warp = tid >> 5;
    int wm = warp >> 1, wn = warp & 1;           // 4 x 2 warp grid
    int g = lane >> 2, tg = lane & 3;
    int arow0 = wm * 32, ncol0 = wn * 40;

    float acc[2][5][4];
#pragma unroll
    for (int t = 0; t < 2; ++t)
#pragma unroll
        for (int u = 0; u < 5; ++u)
#pragma unroll
            for (int v = 0; v < 4; ++v) acc[t][u][v] = 0.f;

    int ar = tid >> 1, acol = (tid & 1) * 4;     // A: 128 rows x 8 cols / float4
    int br = tid >> 1, bcol = (tid & 1) * 4;     // B: 80 rows (br<80 valid)

    // stage chunk 0
    {
        float4 va = *(const float4*)(Z + (size_t)(m0 + ar) * KDIM + acol);
        uint32_t* dh = &AsH[0][ar * 12 + acol];
        uint32_t* dl = &AsL[0][ar * 12 + acol];
        split_tf32(va.x, dh[0], dl[0]); split_tf32(va.y, dh[1], dl[1]);
        split_tf32(va.z, dh[2], dl[2]); split_tf32(va.w, dh[3], dl[3]);
        if (br < BN) {
            float4 vb = *(const float4*)(W + (size_t)(n0 + br) * KDIM + bcol);
            uint32_t* eh = &BsH[0][br * 12 + bcol];
            uint32_t* el = &BsL[0][br * 12 + bcol];
            split_tf32(vb.x, eh[0], el[0]); split_tf32(vb.y, eh[1], el[1]);
            split_tf32(vb.z, eh[2], el[2]); split_tf32(vb.w, eh[3], el[3]);
        }
    }
    __syncthreads();

    for (int kc = 0; kc < KCH; ++kc) {
        int cur = kc & 1;
        float4 pa, pb;
        bool hasNext = (kc + 1 < KCH);
        if (hasNext) {
            int k0 = (kc + 1) * BK;
            pa = *(const float4*)(Z + (size_t)(m0 + ar) * KDIM + k0 + acol);
            if (br < BN) pb = *(const float4*)(W + (size_t)(n0 + br) * KDIM + k0 + bcol);
        }

        uint32_t aH[2][4], aL[2][4], bH[5][2], bL[5][2];
#pragma unroll
        for (int t = 0; t < 2; ++t) {
            int rb = arow0 + t * 16;
            aH[t][0] = AsH[cur][(rb + g) * 12 + tg];
            aH[t][1] = AsH[cur][(rb + g + 8) * 12 + tg];
            aH[t][2] = AsH[cur][(rb + g) * 12 + tg + 4];
            aH[t][3] = AsH[cur][(rb + g + 8) * 12 + tg + 4];
            aL[t][0] = AsL[cur][(rb + g) * 12 + tg];
            aL[t][1] = AsL[cur][(rb + g + 8) * 12 + tg];
            aL[t][2] = AsL[cur][(rb + g) * 12 + tg + 4];
            aL[t][3] = AsL[cur][(rb + g + 8) * 12 + tg + 4];
        }
#pragma unroll
        for (int u = 0; u < 5; ++u) {
            int nb = ncol0 + u * 8;
            bH[u][0] = BsH[cur][(nb + g) * 12 + tg];
            bH[u][1] = BsH[cur][(nb + g) * 12 + tg + 4];
            bL[u][0] = BsL[cur][(nb + g) * 12 + tg];
            bL[u][1] = BsL[cur][(nb + g) * 12 + tg + 4];
        }
        // 3xTF32: small terms first, then dominant term
#pragma unroll
        for (int t = 0; t < 2; ++t)
#pragma unroll
            for (int u = 0; u < 5; ++u) {
                mma_tf32(acc[t][u], aL[t], bH[u]);
                mma_tf32(acc[t][u], aH[t], bL[u]);
                mma_tf32(acc[t][u], aH[t], bH[u]);
            }

        if (hasNext) {
            int nxt = cur ^ 1;
            uint32_t* dh = &AsH[nxt][ar * 12 + acol];
            uint32_t* dl = &AsL[nxt][ar * 12 + acol];
            split_tf32(pa.x, dh[0], dl[0]); split_tf32(pa.y, dh[1], dl[1]);
            split_tf32(pa.z, dh[2], dl[2]); split_tf32(pa.w, dh[3], dl[3]);
            if (br < BN) {
                uint32_t* eh = &BsH[nxt][br * 12 + bcol];
                uint32_t* el = &BsL[nxt][br * 12 + bcol];
                split_tf32(pb.x, eh[0], el[0]); split_tf32(pb.y, eh[1], el[1]);
                split_tf32(pb.z, eh[2], el[2]); split_tf32(pb.w, eh[3], el[3]);
            }
            __syncthreads();
        }
    }

#pragma unroll
    for (int t = 0; t < 2; ++t)
#pragma unroll
        for (int u = 0; u < 5; ++u) {
            int row = m0 + arow0 + t * 16 + g;
            int col = n0 + ncol0 + u * 8 + 2 * tg;
            *(float2*)(G + (size_t)row * GDIM + col)       = make_float2(acc[t][u][0], acc[t][u][1]);
            *(float2*)(G + (size_t)(row + 8) * GDIM + col) = make_float2(acc[t][u][2], acc[t][u][3]);
        }
}

// ---------------- LSTM pointwise --------------------------------------------
__global__ void k_point() {
    int idx = blockIdx.x * blockDim.x + threadIdx.x;
    if (idx >= NB * NF) return;
    int b = idx / NF, u = idx % NF;
    const float* Gr = g_G + (size_t)b * GDIM;
    float i_ = Gr[u]       + g_bias[u];
    float f_ = Gr[200 + u] + g_bias[200 + u];
    float gg = Gr[400 + u] + g_bias[400 + u];
    float o_ = Gr[600 + u] + g_bias[600 + u];
    float c  = g_C[b * NF + u];
    c = sigmoidf_(f_) * c + sigmoidf_(i_) * tanhf(gg);
    float h = sigmoidf_(o_) * tanhf(c);
    g_C[b * NF + u] = c;
    g_Z[b * KDIM + u] = h;          // q = h
    g_Z[b * KDIM + 400 + u] = h;    // hidden for next LSTM
}

// ---------------- fused per-segment softmax attention -----------------------
#define EMAX 1024
__global__ void __launch_bounds__(256) k_attn(const float* __restrict__ x,
                                              float* __restrict__ out, int writeOut) {
    __shared__ float qs[208];
    __shared__ float esm[EMAX];
    __shared__ float red[8];

    int b = blockIdx.x;
    int s0 = g_seg[b], s1 = g_seg[b + 1];
    int L = s1 - s0;
    int tid = threadIdx.x, lane = tid & 31, wid = tid >> 5;

    if (tid < NF) qs[tid] = g_Z[b * KDIM + tid];
    __syncthreads();

    float* eb = (L <= EMAX) ? esm : (g_e + s0);

    // pass 1: e[n] = x[n] . q   (one row per warp, round-robin)
    const float4* q4 = (const float4*)qs;
    float4 qa = q4[lane];
    float4 qb = make_float4(0.f, 0.f, 0.f, 0.f);
    if (lane < 18) qb = q4[32 + lane];
    for (int n = s0 + wid; n < s1; n += 8) {
        const float4* row = (const float4*)(x + (size_t)n * NF);
        float4 va = row[lane];
        float p = va.x * qa.x + va.y * qa.y + va.z * qa.z + va.w * qa.w;
        if (lane < 18) {
            float4 vb = row[32 + lane];
            p += vb.x * qb.x + vb.y * qb.y + vb.z * qb.z + vb.w * qb.w;
        }
#pragma unroll
        for (int o = 16; o > 0; o >>= 1) p += __shfl_down_sync(0xffffffffu, p, o);
        if (lane == 0) eb[n - s0] = p;
    }
    __syncthreads();

    // segment max
    float m = -3.4e38f;
    for (int i = tid; i < L; i += 256) m = fmaxf(m, eb[i]);
#pragma unroll
    for (int o = 16; o > 0; o >>= 1) m = fmaxf(m, __shfl_xor_sync(0xffffffffu, m, o));
    if (lane == 0) red[wid] = m;
    __syncthreads();
    float mm = red[0];
#pragma unroll
    for (int w = 1; w < 8; ++w) mm = fmaxf(mm, red[w]);
    __syncthreads();

    // exp + segment sum
    float s = 0.f;
    for (int i = tid; i < L; i += 256) {
        float p = __expf(eb[i] - mm);
        eb[i] = p;
        s += p;
    }
#pragma unroll
    for (int o = 16; o > 0; o >>= 1) s += __shfl_xor_sync(0xffffffffu, s, o);
    if (lane == 0) red[wid] = s;
    __syncthreads();
    float denom = 0.f;
#pragma unroll
    for (int w = 0; w < 8; ++w) denom += red[w];
    float inv = (L > 0) ? (1.0f / denom) : 0.0f;
    __syncthreads();

    // pass 2: r[f] = inv * sum_n p[n] * x[n][f]   (segment rows are L1/L2-hot)
    if (tid < NF) {
        const float* xp = x + (size_t)s0 * NF + tid;
        float a0 = 0.f, a1 = 0.f, a2 = 0.f, a3 = 0.f;
        int i = 0;
        for (; i + 4 <= L; i += 4) {
            a0 += eb[i + 0] * xp[(size_t)(i + 0) * NF];
            a1 += eb[i + 1] * xp[(size_t)(i + 1) * NF];
            a2 += eb[i + 2] * xp[(size_t)(i + 2) * NF];
            a3 += eb[i + 3] * xp[(size_t)(i + 3) * NF];
        }
        for (; i < L; ++i) a0 += eb[i] * xp[(size_t)i * NF];
        float r = (a0 + a1 + a2 + a3) * inv;
        g_Z[b * KDIM + 200 + tid] = r;
        if (writeOut) {
            out[b * 400 + tid] = qs[tid];       // q
            out[b * 400 + 200 + tid] = r;       // r
        }
    }
}

// ---------------- launch -----------------------------------------------------
extern "C" void kernel_launch(void* const* d_in, const int* in_sizes, int n_in,
                              void* d_out, int out_size) {
    const float* x     = (const float*)d_in[0];
    const int*   batch = (const int*)  d_in[1];
    const float* cosc  = (const float*)d_in[2];
    const float* qstar = (const float*)d_in[3];
    const float* W_ih  = (const float*)d_in[4];
    const float* W_hh  = (const float*)d_in[5];
    const float* b_ih  = (const float*)d_in[6];
    const float* b_hh  = (const float*)d_in[7];
    float* out = (float*)d_out;

    int n = in_sizes[1];  // NTOT

    k_prep  <<<(GDIM * KDIM + GDIM + 255) / 256, 256>>>(W_ih, W_hh, b_ih, b_hh);
    k_bounds<<<(n + 255) / 256, 256>>>(batch, n);
    k_zinit <<<(NB * KDIM + 255) / 256, 256>>>(qstar);
    k_h0    <<<NB, 256>>>(x, cosc);

    for (int s = 0; s < STEPS; ++s) {
        k_gemm <<<dim3(NB / BM, GDIM / BN), 256>>>();
        k_point<<<(NB * NF + 255) / 256, 256>>>();
        k_attn <<<NB, 256>>>(x, out, s == STEPS - 1 ? 1 : 0);
    }
}

// round 3
// speedup vs baseline: 1.5896x; 1.5896x over previous
#include <cuda_runtime.h>
#include <cuda_bf16.h>
#include <cstdint>

// Problem constants (fixed by the dataset)
#define NTOT 131072
#define NB   2048
#define NF   200
#define KDIM 600      // Z row: [q(200) | r(200) | h(200)]
#define GDIM 800      // 4 gates * F
#define STEPS 3

// ---------------- scratch (device globals: no cudaMalloc allowed) ----------
__device__ float g_Z[NB * KDIM];       // A matrix: [q | r | h]
__device__ float g_C[NB * NF];         // LSTM cell state
__device__ float g_G[NB * GDIM];       // gates
__device__ float g_W[GDIM * KDIM];     // Wcat = [W_ih | W_hh]  [800,600] (step 1)
__device__ float g_W2[GDIM * 400];     // folded  [W_ih_q+W_hh | W_ih_r] [800,400] (steps 2,3)
__device__ float g_bias[GDIM];         // b_ih + b_hh
__device__ int   g_seg[NB + 2];        // segment boundaries (batch is sorted)

// ---------------- helpers ---------------------------------------------------
__device__ __forceinline__ uint32_t pack_bf16(float lo, float hi) {
    uint32_t r;
    asm("cvt.rn.bf16x2.f32 %0, %1, %2;" : "=r"(r) : "f"(hi), "f"(lo));
    return r;
}
__device__ __forceinline__ float bf16_round(float v) {
    return __bfloat162float(__float2bfloat16(v));
}

__device__ __forceinline__ void mma_bf16(float d[4], const uint32_t a[4], const uint32_t b[2]) {
    asm volatile(
        "mma.sync.aligned.m16n8k16.row.col.f32.bf16.bf16.f32 "
        "{%0,%1,%2,%3}, {%4,%5,%6,%7}, {%8,%9}, {%0,%1,%2,%3};\n"
        : "+f"(d[0]), "+f"(d[1]), "+f"(d[2]), "+f"(d[3])
        : "r"(a[0]), "r"(a[1]), "r"(a[2]), "r"(a[3]), "r"(b[0]), "r"(b[1]));
}

__device__ __forceinline__ float sigmoidf_(float x) { return 1.0f / (1.0f + expf(-x)); }

// ---------------- prep: Wcat, W2, bias ---------------------------------------
__global__ void k_prep(const float* __restrict__ W_ih, const float* __restrict__ W_hh,
                       const float* __restrict__ b_ih, const float* __restrict__ b_hh) {
    int idx = blockIdx.x * blockDim.x + threadIdx.x;
    const int W1TOT = GDIM * KDIM;            // 480000
    const int W2TOT = GDIM * 400;             // 320000
    if (idx < W1TOT) {
        int j = idx / KDIM, k = idx % KDIM;
        g_W[idx] = (k < 400) ? W_ih[j * 400 + k] : W_hh[j * 200 + (k - 400)];
    } else if (idx < W1TOT + W2TOT) {
        int t = idx - W1TOT;
        int j = t / 400, k = t % 400;
        float v = W_ih[j * 400 + k];
        if (k < 200) v += W_hh[j * 200 + k];
        g_W2[t] = v;
    } else if (idx < W1TOT + W2TOT + GDIM) {
        int j = idx - W1TOT - W2TOT;
        g_bias[j] = b_ih[j] + b_hh[j];
    }
}

// ---------------- segment boundaries (batch sorted) -------------------------
__global__ void k_bounds(const int* __restrict__ batch, int n) {
    int i = blockIdx.x * blockDim.x + threadIdx.x;
    if (i >= n) return;
    int b = batch[i];
    if (i == 0) {
        for (int q = 0; q <= b; ++q) g_seg[q] = 0;
    } else {
        int pb = batch[i - 1];
        for (int q = pb + 1; q <= b; ++q) g_seg[q] = i;
    }
    if (i == n - 1) {
        for (int q = b + 1; q <= NB; ++q) g_seg[q] = n;
    }
}

// ---------------- Z init: Z[:,0:400] = q_star_in, C = 0 ---------------------
__global__ void k_zinit(const float* __restrict__ qstar) {
    int idx = blockIdx.x * blockDim.x + threadIdx.x;
    if (idx >= NB * KDIM) return;
    int b = idx / KDIM, u = idx % KDIM;
    if (u < 400) g_Z[idx] = qstar[b * 400 + u];
    else         g_C[b * NF + (u - 400)] = 0.0f;
}

// ---------------- h0 = segment_sum(cos * x) → Z[:,400:600] ------------------
__global__ void __launch_bounds__(256) k_h0(const float* __restrict__ x,
                                            const float* __restrict__ cosc) {
    __shared__ float part[8][NF];
    int b = blockIdx.x;
    int s0 = g_seg[b], s1 = g_seg[b + 1];
    int tid = threadIdx.x, lane = tid & 31, wid = tid >> 5;

    float4 aA = make_float4(0.f, 0.f, 0.f, 0.f);
    float4 aB = make_float4(0.f, 0.f, 0.f, 0.f);
    for (int n = s0 + wid; n < s1; n += 8) {
        float c = __ldg(cosc + n);
        const float4* row = (const float4*)(x + (size_t)n * NF);
        float4 v = row[lane];
        aA.x += c * v.x; aA.y += c * v.y; aA.z += c * v.z; aA.w += c * v.w;
        if (lane < 18) {
            float4 v2 = row[32 + lane];
            aB.x += c * v2.x; aB.y += c * v2.y; aB.z += c * v2.z; aB.w += c * v2.w;
        }
    }
    part[wid][4 * lane + 0] = aA.x; part[wid][4 * lane + 1] = aA.y;
    part[wid][4 * lane + 2] = aA.z; part[wid][4 * lane + 3] = aA.w;
    if (lane < 18) {
        part[wid][128 + 4 * lane + 0] = aB.x; part[wid][128 + 4 * lane + 1] = aB.y;
        part[wid][128 + 4 * lane + 2] = aB.z; part[wid][128 + 4 * lane + 3] = aB.w;
    }
    __syncthreads();
    if (tid < NF) {
        float s = 0.f;
#pragma unroll
        for (int w = 0; w < 8; ++w) s += part[w][tid];
        g_Z[b * KDIM + 400 + tid] = s;
    }
}

// -------- bf16x3 GEMM: G = Z[2048,K'] @ W'[800,K']^T (fp32-accurate) --------
// K' = 600 (step 1, W = g_W) or 400 (steps 2-3, W = g_W2; uses h == q folding)
#define BM 128
#define BN 80
#define BKF 16                 // K elements per chunk
#define SST 12                 // smem row stride in u32 (conflict-free)

template<int K, int KCH>
__global__ void __launch_bounds__(256) k_gemm(const float* __restrict__ W) {
    __shared__ uint32_t AsH[2][BM * SST];
    __shared__ uint32_t AsL[2][BM * SST];
    __shared__ uint32_t BsH[2][BN * SST];
    __shared__ uint32_t BsL[2][BN * SST];

    const float* Z = g_Z;
    float* G = g_G;

    int m0 = blockIdx.x * BM, n0 = blockIdx.y * BN;
    int tid = threadIdx.x, lane = tid & 31, warp = tid >> 5;
    int wm = warp >> 1, wn = warp & 1;           // 4 x 2 warp grid
    int g = lane >> 2, tg = lane & 3;
    int arow0 = wm * 32, ncol0 = wn * 40;

    float acc[2][5][4];
#pragma unroll
    for (int t = 0; t < 2; ++t)
#pragma unroll
        for (int u = 0; u < 5; ++u)
#pragma unroll
            for (int v = 0; v < 4; ++v) acc[t][u][v] = 0.f;

    int ar = tid >> 1;                 // A row within tile (2 threads/row)
    int br = tid >> 1;                 // B row within tile (valid < BN)
    int koff = (tid & 1) * 8;          // float offset within 16-wide chunk
    int uoff = (tid & 1) * 4;          // u32 offset

    const float* Arow = Z + (size_t)(m0 + ar) * KDIM;
    const float* Brow = W + (size_t)(n0 + br) * K;

    // stage helper (lambda-free): loads 8 floats (or zeros past K), splits hi/lo
    auto stage = [&](int buf, int k0f, float4 va0, float4 va1, float4 vb0, float4 vb1) {
        float av[8] = {va0.x, va0.y, va0.z, va0.w, va1.x, va1.y, va1.z, va1.w};
        uint32_t* dh = &AsH[buf][ar * SST + uoff];
        uint32_t* dl = &AsL[buf][ar * SST + uoff];
#pragma unroll
        for (int i = 0; i < 4; ++i) {
            float a = av[2 * i], b = av[2 * i + 1];
            float ah = bf16_round(a), bh = bf16_round(b);
            dh[i] = pack_bf16(ah, bh);
            dl[i] = pack_bf16(a - ah, b - bh);
        }
        if (br < BN) {
            float bv[8] = {vb0.x, vb0.y, vb0.z, vb0.w, vb1.x, vb1.y, vb1.z, vb1.w};
            uint32_t* eh = &BsH[buf][br * SST + uoff];
            uint32_t* el = &BsL[buf][br * SST + uoff];
#pragma unroll
            for (int i = 0; i < 4; ++i) {
                float a = bv[2 * i], b = bv[2 * i + 1];
                float ah = bf16_round(a), bh = bf16_round(b);
                eh[i] = pack_bf16(ah, bh);
                el[i] = pack_bf16(a - ah, b - bh);
            }
        }
    };

    auto ld8 = [&](const float* base, int k0, float4& v0, float4& v1) {
        if (k0 + 8 <= K) {
            v0 = *(const float4*)(base + k0);
            v1 = *(const float4*)(base + k0 + 4);
        } else {
            v0 = make_float4(0.f, 0.f, 0.f, 0.f);
            v1 = make_float4(0.f, 0.f, 0.f, 0.f);
        }
    };

    // stage chunk 0
    {
        float4 a0, a1, b0, b1;
        ld8(Arow, koff, a0, a1);
        if (br < BN) ld8(Brow, koff, b0, b1); else { b0 = b1 = make_float4(0,0,0,0); }
        stage(0, 0, a0, a1, b0, b1);
    }
    __syncthreads();

    for (int kc = 0; kc < KCH; ++kc) {
        int cur = kc & 1;
        float4 pa0, pa1, pb0, pb1;
        bool hasNext = (kc + 1 < KCH);
        if (hasNext) {
            int k0 = (kc + 1) * BKF + koff;
            ld8(Arow, k0, pa0, pa1);
            if (br < BN) ld8(Brow, k0, pb0, pb1); else { pb0 = pb1 = make_float4(0,0,0,0); }
        }

        uint32_t aH[2][4], aL[2][4], bH[5][2], bL[5][2];
#pragma unroll
        for (int t = 0; t < 2; ++t) {
            int rb = arow0 + t * 16;
            aH[t][0] = AsH[cur][(rb + g) * SST + tg];
            aH[t][1] = AsH[cur][(rb + g + 8) * SST + tg];
            aH[t][2] = AsH[cur][(rb + g) * SST + tg + 4];
            aH[t][3] = AsH[cur][(rb + g + 8) * SST + tg + 4];
            aL[t][0] = AsL[cur][(rb + g) * SST + tg];
            aL[t][1] = AsL[cur][(rb + g + 8) * SST + tg];
            aL[t][2] = AsL[cur][(rb + g) * SST + tg + 4];
            aL[t][3] = AsL[cur][(rb + g + 8) * SST + tg + 4];
        }
#pragma unroll
        for (int u = 0; u < 5; ++u) {
            int nb = ncol0 + u * 8;
            bH[u][0] = BsH[cur][(nb + g) * SST + tg];
            bH[u][1] = BsH[cur][(nb + g) * SST + tg + 4];
            bL[u][0] = BsL[cur][(nb + g) * SST + tg];
            bL[u][1] = BsL[cur][(nb + g) * SST + tg + 4];
        }
        // bf16x3: cross terms first, dominant last
#pragma unroll
        for (int t = 0; t < 2; ++t)
#pragma unroll
            for (int u = 0; u < 5; ++u) {
                mma_bf16(acc[t][u], aL[t], bH[u]);
                mma_bf16(acc[t][u], aH[t], bL[u]);
                mma_bf16(acc[t][u], aH[t], bH[u]);
            }

        if (hasNext) {
            __syncthreads();           // buffer nxt free (consumed 2 chunks ago)
            stage(cur ^ 1, 0, pa0, pa1, pb0, pb1);
            __syncthreads();
        }
    }

#pragma unroll
    for (int t = 0; t < 2; ++t)
#pragma unroll
        for (int u = 0; u < 5; ++u) {
            int row = m0 + arow0 + t * 16 + g;
            int col = n0 + ncol0 + u * 8 + 2 * tg;
            *(float2*)(G + (size_t)row * GDIM + col)       = make_float2(acc[t][u][0], acc[t][u][1]);
            *(float2*)(G + (size_t)(row + 8) * GDIM + col) = make_float2(acc[t][u][2], acc[t][u][3]);
        }
}

// ---------------- LSTM pointwise --------------------------------------------
__global__ void k_point() {
    int idx = blockIdx.x * blockDim.x + threadIdx.x;
    if (idx >= NB * NF) return;
    int b = idx / NF, u = idx % NF;
    const float* Gr = g_G + (size_t)b * GDIM;
    float i_ = Gr[u]       + g_bias[u];
    float f_ = Gr[200 + u] + g_bias[200 + u];
    float gg = Gr[400 + u] + g_bias[400 + u];
    float o_ = Gr[600 + u] + g_bias[600 + u];
    float c  = g_C[b * NF + u];
    c = sigmoidf_(f_) * c + sigmoidf_(i_) * tanhf(gg);
    float h = sigmoidf_(o_) * tanhf(c);
    g_C[b * NF + u] = c;
    g_Z[b * KDIM + u] = h;   // q = h  (steps 2-3 GEMM uses folded W2, no h slot needed)
}

// ------ fused single-pass (online softmax) per-segment attention ------------
__global__ void __launch_bounds__(256) k_attn(const float* __restrict__ x,
                                              float* __restrict__ out, int writeOut) {
    __shared__ float qs[208];
    __shared__ float part[8][NF];
    __shared__ float pm[8], ps[8], fac[8];

    int b = blockIdx.x;
    int s0 = g_seg[b], s1 = g_seg[b + 1];
    int tid = threadIdx.x, lane = tid & 31, wid = tid >> 5;

    if (tid < NF) qs[tid] = g_Z[b * KDIM + tid];
    __syncthreads();

    const float4* q4 = (const float4*)qs;
    float4 qa = q4[lane];
    float4 qb = make_float4(0.f, 0.f, 0.f, 0.f);
    if (lane < 18) qb = q4[32 + lane];

    float4 ra = make_float4(0.f, 0.f, 0.f, 0.f);
    float4 rb = make_float4(0.f, 0.f, 0.f, 0.f);
    float run_m = -3.0e38f, run_s = 0.f;

    for (int n = s0 + wid; n < s1; n += 8) {
        const float4* row = (const float4*)(x + (size_t)n * NF);
        float4 va = row[lane];
        float4 vb = make_float4(0.f, 0.f, 0.f, 0.f);
        float p = va.x * qa.x + va.y * qa.y + va.z * qa.z + va.w * qa.w;
        if (lane < 18) {
            vb = row[32 + lane];
            p += vb.x * qb.x + vb.y * qb.y + vb.z * qb.z + vb.w * qb.w;
        }
#pragma unroll
        for (int o = 16; o > 0; o >>= 1) p += __shfl_xor_sync(0xffffffffu, p, o);
        // online softmax update (all lanes have same p)
        if (p > run_m) {
            float sc = __expf(run_m - p);
            ra.x *= sc; ra.y *= sc; ra.z *= sc; ra.w *= sc;
            rb.x *= sc; rb.y *= sc; rb.z *= sc; rb.w *= sc;
            run_s *= sc;
            run_m = p;
        }
        float w = __expf(p - run_m);
        run_s += w;
        ra.x += w * va.x; ra.y += w * va.y; ra.z += w * va.z; ra.w += w * va.w;
        rb.x += w * vb.x; rb.y += w * vb.y; rb.z += w * vb.z; rb.w += w * vb.w;
    }

    part[wid][4 * lane + 0] = ra.x; part[wid][4 * lane + 1] = ra.y;
    part[wid][4 * lane + 2] = ra.z; part[wid][4 * lane + 3] = ra.w;
    if (lane < 18) {
        part[wid][128 + 4 * lane + 0] = rb.x; part[wid][128 + 4 * lane + 1] = rb.y;
        part[wid][128 + 4 * lane + 2] = rb.z; part[wid][128 + 4 * lane + 3] = rb.w;
    }
    if (lane == 0) { pm[wid] = run_m; ps[wid] = run_s; }
    __syncthreads();

    if (tid < 8) {
        float M = pm[0];
#pragma unroll
        for (int w = 1; w < 8; ++w) M = fmaxf(M, pm[w]);
        fac[tid] = __expf(pm[tid] - M);
    }
    __syncthreads();

    if (tid < NF) {
        float denom = 0.f, r = 0.f;
#pragma unroll
        for (int w = 0; w < 8; ++w) {
            denom += fac[w] * ps[w];
            r     += fac[w] * part[w][tid];
        }
        r = (denom > 0.f) ? (r / denom) : 0.f;
        g_Z[b * KDIM + 200 + tid] = r;
        if (writeOut) {
            out[b * 400 + tid] = qs[tid];       // q
            out[b * 400 + 200 + tid] = r;       // r
        }
    }
}

// ---------------- launch -----------------------------------------------------
extern "C" void kernel_launch(void* const* d_in, const int* in_sizes, int n_in,
                              void* d_out, int out_size) {
    const float* x     = (const float*)d_in[0];
    const int*   batch = (const int*)  d_in[1];
    const float* cosc  = (const float*)d_in[2];
    const float* qstar = (const float*)d_in[3];
    const float* W_ih  = (const float*)d_in[4];
    const float* W_hh  = (const float*)d_in[5];
    const float* b_ih  = (const float*)d_in[6];
    const float* b_hh  = (const float*)d_in[7];
    float* out = (float*)d_out;

    int n = in_sizes[1];  // NTOT

    const int prepTot = GDIM * KDIM + GDIM * 400 + GDIM;
    k_prep  <<<(prepTot + 255) / 256, 256>>>(W_ih, W_hh, b_ih, b_hh);
    k_bounds<<<(n + 255) / 256, 256>>>(batch, n);
    k_zinit <<<(NB * KDIM + 255) / 256, 256>>>(qstar);
    k_h0    <<<NB, 256>>>(x, cosc);

    dim3 ggrid(NB / BM, GDIM / BN);
    float* w1; cudaGetSymbolAddress((void**)&w1, g_W);
    float* w2; cudaGetSymbolAddress((void**)&w2, g_W2);

    for (int s = 0; s < STEPS; ++s) {
        if (s == 0) k_gemm<600, 38><<<ggrid, 256>>>(w1);
        else        k_gemm<400, 25><<<ggrid, 256>>>(w2);
        k_point<<<(NB * NF + 255) / 256, 256>>>();
        k_attn <<<NB, 256>>>(x, out, s == STEPS - 1 ? 1 : 0);
    }
}

// round 5
// speedup vs baseline: 1.9772x; 1.2438x over previous
#include <cuda_runtime.h>
#include <cuda_bf16.h>
#include <cstdint>

// Problem constants
#define NTOT 131072
#define NB   2048
#define NF   200
#define GDIM 800
#define STEPS 3

// bf16x3 via K-concatenation (plain bf16 GEMM)
// step 1:  A=[ (qstar|h)H pad→640 | lo | hi ], K=1920 ; W sections [H|H|L]
// steps 2-3 (h==q folding): sections of 448 from [q(200)|r(200)|pad48], K=1344
#define KB1 1920
#define KB2 1344
#define SEC1 640
#define SEC2 448
#define NCH1 30          // K chunks of 64
#define NCH2 21
#define GM 128           // CTA M tile
#define GNT 80           // CTA N tile (20 units x 4 gates, interleaved)
#define NU 20
#define NSTAGE 3
#define STG 26624        // stage bytes: A 128x64 bf16 (16384) + B 80x64 bf16 (10240)
#define SOFF 1024

// ---------------- scratch ----------------------------------------------------
__device__ __nv_bfloat16 g_Zb1[NB * KB1];
__device__ __nv_bfloat16 g_Zb2[NB * KB2];
__device__ __nv_bfloat16 g_Wb1[GDIM * KB1];   // permuted rows jp = u*4+gate
__device__ __nv_bfloat16 g_Wb2[GDIM * KB2];
__device__ float g_biasP[GDIM];               // permuted bias
__device__ float g_Z[NB * NF];                // q (fp32) for attention
__device__ float g_C[NB * NF];                // LSTM cell state
__device__ int   g_seg[NB + 2];

// ---------------- helpers ----------------------------------------------------
__device__ __forceinline__ uint32_t smem_u32(const void* p) {
    return (uint32_t)__cvta_generic_to_shared(p);
}
__device__ __forceinline__ float sigmoidf_(float x) { return 1.0f / (1.0f + expf(-x)); }

__device__ __forceinline__ void cp16(uint32_t dst, const void* src) {
    asm volatile("cp.async.cg.shared.global [%0], [%1], 16;" :: "r"(dst), "l"(src) : "memory");
}
#define CP_COMMIT() asm volatile("cp.async.commit_group;" ::: "memory")

__device__ __forceinline__ void mma_bf16(float d[4], const uint32_t a[4], const uint32_t b[2]) {
    asm volatile(
        "mma.sync.aligned.m16n8k16.row.col.f32.bf16.bf16.f32 "
        "{%0,%1,%2,%3}, {%4,%5,%6,%7}, {%8,%9}, {%0,%1,%2,%3};\n"
        : "+f"(d[0]), "+f"(d[1]), "+f"(d[2]), "+f"(d[3])
        : "r"(a[0]), "r"(a[1]), "r"(a[2]), "r"(a[3]), "r"(b[0]), "r"(b[1]));
}

// ---------------- prep: permuted+split weights & bias -------------------------
__global__ void k_prep(const float* __restrict__ W_ih, const float* __restrict__ W_hh,
                       const float* __restrict__ b_ih, const float* __restrict__ b_hh) {
    int idx = blockIdx.x * blockDim.x + threadIdx.x;
    const int RW1 = GDIM * KB1;
    const int RW2 = RW1 + GDIM * KB2;
    if (idx < RW1) {
        int jp = idx / KB1, u = idx % KB1;
        int j = (jp & 3) * 200 + (jp >> 2);       // jp = unit*4 + gate
        int s = u / SEC1, k = u % SEC1;
        float a = 0.f;
        if (k < 400)      a = W_ih[j * 400 + k];
        else if (k < 600) a = W_hh[j * 200 + (k - 400)];
        __nv_bfloat16 hi = __float2bfloat16(a);
        g_Wb1[idx] = (s < 2) ? hi : __float2bfloat16(a - __bfloat162float(hi));
    } else if (idx < RW2) {
        int t = idx - RW1;
        int jp = t / KB2, u = t % KB2;
        int j = (jp & 3) * 200 + (jp >> 2);
        int s = u / SEC2, k = u % SEC2;
        float a = 0.f;
        if (k < 400) {
            a = W_ih[j * 400 + k];
            if (k < 200) a += W_hh[j * 200 + k];
        }
        __nv_bfloat16 hi = __float2bfloat16(a);
        g_Wb2[t] = (s < 2) ? hi : __float2bfloat16(a - __bfloat162float(hi));
    } else if (idx < RW2 + GDIM) {
        int jp = idx - RW2;
        int j = (jp & 3) * 200 + (jp >> 2);
        g_biasP[jp] = b_ih[j] + b_hh[j];
    }
}

// ---------------- segment boundaries -----------------------------------------
__global__ void k_bounds(const int* __restrict__ batch, int n) {
    int i = blockIdx.x * blockDim.x + threadIdx.x;
    if (i >= n) return;
    int b = batch[i];
    if (i == 0) { for (int q = 0; q <= b; ++q) g_seg[q] = 0; }
    else {
        int pb = batch[i - 1];
        for (int q = pb + 1; q <= b; ++q) g_seg[q] = i;
    }
    if (i == n - 1) { for (int q = b + 1; q <= NB; ++q) g_seg[q] = n; }
}

// ---------------- init: Zb1 q_star sections, C=0, Zb2 pads --------------------
__global__ void k_zinit(const float* __restrict__ qstar) {
    int idx = blockIdx.x * blockDim.x + threadIdx.x;
    const int R1 = NB * KB1;
    const int R2 = R1 + NB * NF;
    const int R3 = R2 + NB * 144;
    if (idx < R1) {
        int b = idx / KB1, u = idx % KB1;
        int s = u / SEC1, k = u % SEC1;
        if (k < 400) {
            float v = qstar[b * 400 + k];
            __nv_bfloat16 hi = __float2bfloat16(v);
            g_Zb1[idx] = (s == 1) ? __float2bfloat16(v - __bfloat162float(hi)) : hi;
        } else if (k >= 600) {
            g_Zb1[idx] = __float2bfloat16(0.f);
        } // 400..599 written by k_h0
    } else if (idx < R2) {
        g_C[idx - R1] = 0.f;
    } else if (idx < R3) {
        int t = idx - R2;
        int b = t / 144, k = t % 144;
        int sec = k / 48;
        g_Zb2[b * KB2 + sec * SEC2 + 400 + (k % 48)] = __float2bfloat16(0.f);
    }
}

// ---------------- h0 = segment_sum(cos*x) → Zb1 h sections --------------------
__global__ void __launch_bounds__(256) k_h0(const float* __restrict__ x,
                                            const float* __restrict__ cosc) {
    __shared__ float part[8][NF];
    int b = blockIdx.x;
    int s0 = g_seg[b], s1 = g_seg[b + 1];
    int tid = threadIdx.x, lane = tid & 31, wid = tid >> 5;

    float4 aA = make_float4(0.f, 0.f, 0.f, 0.f);
    float4 aB = make_float4(0.f, 0.f, 0.f, 0.f);
    for (int n = s0 + wid; n < s1; n += 8) {
        float c = __ldg(cosc + n);
        const float4* row = (const float4*)(x + (size_t)n * NF);
        float4 v = row[lane];
        aA.x += c * v.x; aA.y += c * v.y; aA.z += c * v.z; aA.w += c * v.w;
        if (lane < 18) {
            float4 v2 = row[32 + lane];
            aB.x += c * v2.x; aB.y += c * v2.y; aB.z += c * v2.z; aB.w += c * v2.w;
        }
    }
    part[wid][4 * lane + 0] = aA.x; part[wid][4 * lane + 1] = aA.y;
    part[wid][4 * lane + 2] = aA.z; part[wid][4 * lane + 3] = aA.w;
    if (lane < 18) {
        part[wid][128 + 4 * lane + 0] = aB.x; part[wid][128 + 4 * lane + 1] = aB.y;
        part[wid][128 + 4 * lane + 2] = aB.z; part[wid][128 + 4 * lane + 3] = aB.w;
    }
    __syncthreads();
    if (tid < NF) {
        float s = 0.f;
#pragma unroll
        for (int w = 0; w < 8; ++w) s += part[w][tid];
        __nv_bfloat16 hi = __float2bfloat16(s);
        __nv_bfloat16 lo = __float2bfloat16(s - __bfloat162float(hi));
        size_t base = (size_t)b * KB1;
        g_Zb1[base + 400 + tid] = hi;
        g_Zb1[base + SEC1 + 400 + tid] = lo;
        g_Zb1[base + 2 * SEC1 + 400 + tid] = hi;
    }
}

// -------- mma.sync bf16 GEMM (CTA 128x80) + fused LSTM pointwise --------------
template<int KB, int NCHUNK>
__global__ void __launch_bounds__(256, 2) k_gemm_fused(const __nv_bfloat16* __restrict__ A,
                                                       const __nv_bfloat16* __restrict__ Wb) {
    extern __shared__ char smem[];
    uint32_t sbase = smem_u32(smem);
    float* sBias = (float*)smem;                 // 80 floats at offset 0
    int tid = threadIdx.x, lane = tid & 31, warp = tid >> 5;
    int m0 = blockIdx.x * GM;
    int bn = blockIdx.y;
    int n0 = bn * GNT;
    if (tid < GNT) sBias[tid] = g_biasP[n0 + tid];

    int wm = warp >> 1, wn = warp & 1;           // 4 x 2 warp grid
    int r7 = lane & 7, quad = lane >> 3;
    int gg = lane >> 2, t4 = lane & 3;

    float acc[2][5][4];
#pragma unroll
    for (int t = 0; t < 2; ++t)
#pragma unroll
        for (int u = 0; u < 5; ++u)
#pragma unroll
            for (int v = 0; v < 4; ++v) acc[t][u][v] = 0.f;

    // chunk loader: A[128x64] + B[80x64] bf16, SW128 swizzle, cp.async 16B
    auto load_chunk = [&](int c) {
        int s = c % NSTAGE;
        uint32_t aBase = sbase + SOFF + s * STG;
        uint32_t bBase = aBase + 16384;
        const __nv_bfloat16* gA = A + (size_t)m0 * KB + c * 64;
        const __nv_bfloat16* gW = Wb + (size_t)n0 * KB + c * 64;
#pragma unroll
        for (int i = 0; i < 4; ++i) {            // 128*8 / 256
            int t = tid + i * 256;
            int r = t >> 3, v = t & 7;
            uint32_t bo = (uint32_t)r * 128 + v * 16;
            cp16(aBase + (bo ^ ((r & 7) << 4)), gA + (size_t)r * KB + v * 8);
        }
        for (int t = tid; t < 80 * 8; t += 256) {
            int r = t >> 3, v = t & 7;
            uint32_t bo = (uint32_t)r * 128 + v * 16;
            cp16(bBase + (bo ^ ((r & 7) << 4)), gW + (size_t)r * KB + v * 8);
        }
        CP_COMMIT();
    };

    auto compute = [&](int slot) {
        uint32_t aB = sbase + SOFF + slot * STG;
        uint32_t bB = aB + 16384;
#pragma unroll
        for (int k16 = 0; k16 < 4; ++k16) {
            int kb = k16 * 32;                   // byte offset of k16 within chunk
            uint32_t aF[2][4], bF[5][2];
#pragma unroll
            for (int t = 0; t < 2; ++t) {
                int row = wm * 32 + t * 16 + (quad & 1) * 8 + r7;
                int cb = kb + (quad >> 1) * 16;
                uint32_t ad = aB + (((uint32_t)row * 128 + cb) ^ ((row & 7) << 4));
                asm volatile("ldmatrix.sync.aligned.m8n8.x4.shared.b16 {%0,%1,%2,%3}, [%4];"
                             : "=r"(aF[t][0]), "=r"(aF[t][1]), "=r"(aF[t][2]), "=r"(aF[t][3])
                             : "r"(ad));
            }
#pragma unroll
            for (int p = 0; p < 2; ++p) {        // n8 tiles (2p, 2p+1)
                int row = wn * 40 + (2 * p + (quad >> 1)) * 8 + r7;
                int cb = kb + (quad & 1) * 16;
                uint32_t bd = bB + (((uint32_t)row * 128 + cb) ^ ((row & 7) << 4));
                asm volatile("ldmatrix.sync.aligned.m8n8.x4.shared.b16 {%0,%1,%2,%3}, [%4];"
                             : "=r"(bF[2 * p][0]), "=r"(bF[2 * p][1]),
                               "=r"(bF[2 * p + 1][0]), "=r"(bF[2 * p + 1][1])
                             : "r"(bd));
            }
            {
                int row = wn * 40 + 32 + r7;
                int cb = kb + (quad & 1) * 16;
                uint32_t bd = bB + (((uint32_t)row * 128 + cb) ^ ((row & 7) << 4));
                asm volatile("ldmatrix.sync.aligned.m8n8.x2.shared.b16 {%0,%1}, [%2];"
                             : "=r"(bF[4][0]), "=r"(bF[4][1]) : "r"(bd));
            }
#pragma unroll
            for (int t = 0; t < 2; ++t)
#pragma unroll
                for (int u = 0; u < 5; ++u) mma_bf16(acc[t][u], aF[t], bF[u]);
        }
    };

    load_chunk(0);
    load_chunk(1);
    for (int c = 0; c < NCHUNK; ++c) {
        if (c + 1 < NCHUNK) asm volatile("cp.async.wait_group 1;" ::: "memory");
        else                asm volatile("cp.async.wait_group 0;" ::: "memory");
        __syncthreads();
        if (c + 2 < NCHUNK) load_chunk(c + 2);
        compute(c % NSTAGE);
    }
    __syncthreads();

    // ---- epilogue: gates → smem, then fused LSTM pointwise -------------------
    float* sG = (float*)(smem + SOFF);           // [128][88] fp32, overlays stages
#pragma unroll
    for (int t = 0; t < 2; ++t)
#pragma unroll
        for (int u = 0; u < 5; ++u) {
            int r0 = wm * 32 + t * 16 + gg;
            int cb = wn * 40 + u * 8 + 2 * t4;
            *(float2*)&sG[r0 * 88 + cb]       = make_float2(acc[t][u][0], acc[t][u][1]);
            *(float2*)&sG[(r0 + 8) * 88 + cb] = make_float2(acc[t][u][2], acc[t][u][3]);
        }
    __syncthreads();

    for (int it = tid; it < GM * NU; it += 256) {
        int row = it / NU, ul = it % NU;
        int b = m0 + row;
        float4 gv = *(float4*)&sG[row * 88 + 4 * ul];
        float i_ = gv.x + sBias[4 * ul + 0];
        float f_ = gv.y + sBias[4 * ul + 1];
        float g_ = gv.z + sBias[4 * ul + 2];
        float o_ = gv.w + sBias[4 * ul + 3];
        int ug = bn * NU + ul;
        float c = g_C[(size_t)b * NF + ug];
        c = sigmoidf_(f_) * c + sigmoidf_(i_) * tanhf(g_);
        float h = sigmoidf_(o_) * tanhf(c);
        g_C[(size_t)b * NF + ug] = c;
        g_Z[(size_t)b * NF + ug] = h;
        __nv_bfloat16 hi = __float2bfloat16(h);
        __nv_bfloat16 lo = __float2bfloat16(h - __bfloat162float(hi));
        __nv_bfloat16* Zr = g_Zb2 + (size_t)b * KB2;
        Zr[ug] = hi; Zr[SEC2 + ug] = lo; Zr[2 * SEC2 + ug] = hi;
    }
}

// ------ fused single-pass (online softmax) per-segment attention --------------
__global__ void __launch_bounds__(256) k_attn(const float* __restrict__ x,
                                              float* __restrict__ out, int writeOut) {
    __shared__ float qs[208];
    __shared__ float part[8][NF];
    __shared__ float pm[8], ps[8], fac[8];

    int b = blockIdx.x;
    int s0 = g_seg[b], s1 = g_seg[b + 1];
    int tid = threadIdx.x, lane = tid & 31, wid = tid >> 5;

    if (tid < NF) qs[tid] = g_Z[b * NF + tid];
    __syncthreads();

    const float4* q4 = (const float4*)qs;
    float4 qa = q4[lane];
    float4 qb = make_float4(0.f, 0.f, 0.f, 0.f);
    if (lane < 18) qb = q4[32 + lane];

    float4 ra = make_float4(0.f, 0.f, 0.f, 0.f);
    float4 rb = make_float4(0.f, 0.f, 0.f, 0.f);
    float run_m = -3.0e38f, run_s = 0.f;

    for (int n = s0 + wid; n < s1; n += 8) {
        const float4* row = (const float4*)(x + (size_t)n * NF);
        float4 va = row[lane];
        float4 vb = make_float4(0.f, 0.f, 0.f, 0.f);
        float p = va.x * qa.x + va.y * qa.y + va.z * qa.z + va.w * qa.w;
        if (lane < 18) {
            vb = row[32 + lane];
            p += vb.x * qb.x + vb.y * qb.y + vb.z * qb.z + vb.w * qb.w;
        }
#pragma unroll
        for (int o = 16; o > 0; o >>= 1) p += __shfl_xor_sync(0xffffffffu, p, o);
        if (p > run_m) {
            float sc = __expf(run_m - p);
            ra.x *= sc; ra.y *= sc; ra.z *= sc; ra.w *= sc;
            rb.x *= sc; rb.y *= sc; rb.z *= sc; rb.w *= sc;
            run_s *= sc;
            run_m = p;
        }
        float w = __expf(p - run_m);
        run_s += w;
        ra.x += w * va.x; ra.y += w * va.y; ra.z += w * va.z; ra.w += w * va.w;
        rb.x += w * vb.x; rb.y += w * vb.y; rb.z += w * vb.z; rb.w += w * vb.w;
    }

    part[wid][4 * lane + 0] = ra.x; part[wid][4 * lane + 1] = ra.y;
    part[wid][4 * lane + 2] = ra.z; part[wid][4 * lane + 3] = ra.w;
    if (lane < 18) {
        part[wid][128 + 4 * lane + 0] = rb.x; part[wid][128 + 4 * lane + 1] = rb.y;
        part[wid][128 + 4 * lane + 2] = rb.z; part[wid][128 + 4 * lane + 3] = rb.w;
    }
    if (lane == 0) { pm[wid] = run_m; ps[wid] = run_s; }
    __syncthreads();

    if (tid < 8) {
        float M = pm[0];
#pragma unroll
        for (int w = 1; w < 8; ++w) M = fmaxf(M, pm[w]);
        fac[tid] = __expf(pm[tid] - M);
    }
    __syncthreads();

    if (tid < NF) {
        float denom = 0.f, r = 0.f;
#pragma unroll
        for (int w = 0; w < 8; ++w) {
            denom += fac[w] * ps[w];
            r     += fac[w] * part[w][tid];
        }
        r = (denom > 0.f) ? (r / denom) : 0.f;
        __nv_bfloat16 hi = __float2bfloat16(r);
        __nv_bfloat16 lo = __float2bfloat16(r - __bfloat162float(hi));
        size_t base = (size_t)b * KB2 + 200 + tid;
        g_Zb2[base] = hi;
        g_Zb2[base + SEC2] = lo;
        g_Zb2[base + 2 * SEC2] = hi;
        if (writeOut) {
            out[b * 400 + tid] = qs[tid];
            out[b * 400 + 200 + tid] = r;
        }
    }
}

// ---------------- launch --------------------------------------------------------
extern "C" void kernel_launch(void* const* d_in, const int* in_sizes, int n_in,
                              void* d_out, int out_size) {
    const float* x     = (const float*)d_in[0];
    const int*   batch = (const int*)  d_in[1];
    const float* cosc  = (const float*)d_in[2];
    const float* qstar = (const float*)d_in[3];
    const float* W_ih  = (const float*)d_in[4];
    const float* W_hh  = (const float*)d_in[5];
    const float* b_ih  = (const float*)d_in[6];
    const float* b_hh  = (const float*)d_in[7];
    float* out = (float*)d_out;

    int n = in_sizes[1];

    const int smemBytes = SOFF + NSTAGE * STG;   // 80896
    static bool attrSet = false;
    cudaFuncSetAttribute(k_gemm_fused<KB1, NCH1>,
                         cudaFuncAttributeMaxDynamicSharedMemorySize, smemBytes);
    cudaFuncSetAttribute(k_gemm_fused<KB2, NCH2>,
                         cudaFuncAttributeMaxDynamicSharedMemorySize, smemBytes);
    (void)attrSet;

    __nv_bfloat16 *zb1, *zb2, *wb1, *wb2;
    cudaGetSymbolAddress((void**)&zb1, g_Zb1);
    cudaGetSymbolAddress((void**)&zb2, g_Zb2);
    cudaGetSymbolAddress((void**)&wb1, g_Wb1);
    cudaGetSymbolAddress((void**)&wb2, g_Wb2);

    const int prepTot = GDIM * KB1 + GDIM * KB2 + GDIM;
    k_prep  <<<(prepTot + 255) / 256, 256>>>(W_ih, W_hh, b_ih, b_hh);
    k_bounds<<<(n + 255) / 256, 256>>>(batch, n);
    const int zTot = NB * KB1 + NB * NF + NB * 144;
    k_zinit <<<(zTot + 255) / 256, 256>>>(qstar);
    k_h0    <<<NB, 256>>>(x, cosc);

    dim3 ggrid(NB / GM, GDIM / GNT);             // 16 x 10 = 160 CTAs
    for (int s = 0; s < STEPS; ++s) {
        if (s == 0) k_gemm_fused<KB1, NCH1><<<ggrid, 256, smemBytes>>>(zb1, wb1);
        else        k_gemm_fused<KB2, NCH2><<<ggrid, 256, smemBytes>>>(zb2, wb2);
        k_attn<<<NB, 256>>>(x, out, s == STEPS - 1 ? 1 : 0);
    }
}

// round 7
// speedup vs baseline: 2.0024x; 1.0128x over previous
#include <cuda_runtime.h>
#include <cuda_bf16.h>
#include <cstdint>

// Problem constants
#define NTOT 131072
#define NB   2048
#define NF   200
#define GDIM 800
#define STEPS 3

// bf16x3 via K-concatenation (plain bf16 GEMM)
#define KB1 1920
#define KB2 1344
#define SEC1 640
#define SEC2 448
#define NCH1 30          // K chunks of 64
#define NCH2 21
#define GM 128
#define GNT 80
#define NSPLIT 4
#define NSTAGE 3
#define STG 26624        // A 128x64 bf16 (16384) + B 80x64 bf16 (10240)
#define SOFF 1024

// ---------------- scratch ----------------------------------------------------
__device__ __nv_bfloat16 g_Zb1[NB * KB1];
__device__ __nv_bfloat16 g_Zb2[NB * KB2];
__device__ __nv_bfloat16 g_Wb1[GDIM * KB1];   // permuted rows jp = unit*4+gate
__device__ __nv_bfloat16 g_Wb2[GDIM * KB2];
__device__ float g_biasP[GDIM];
__device__ float g_Z[NB * NF];                // q (fp32) for attention
__device__ float g_C[NB * NF];                // LSTM cell state
__device__ float g_Gp[NSPLIT * NB * GDIM];    // split-K partials
__device__ int   g_seg[NB + 2];

// ---------------- helpers ----------------------------------------------------
__device__ __forceinline__ uint32_t smem_u32(const void* p) {
    return (uint32_t)__cvta_generic_to_shared(p);
}
__device__ __forceinline__ float sigmoidf_(float x) { return 1.0f / (1.0f + expf(-x)); }

__device__ __forceinline__ void cp16(uint32_t dst, const void* src) {
    asm volatile("cp.async.cg.shared.global [%0], [%1], 16;" :: "r"(dst), "l"(src) : "memory");
}
#define CP_COMMIT() asm volatile("cp.async.commit_group;" ::: "memory")

// x loads: keep resident in L2 across passes (cache-hint form; the immediate
// .L2::evict_last qualifier is rejected for v4.f32 by ptxas on compute_103)
__device__ __forceinline__ uint64_t mk_policy() {
    uint64_t pol;
    asm volatile("createpolicy.fractional.L2::evict_last.b64 %0, 1.0;" : "=l"(pol));
    return pol;
}
__device__ __forceinline__ float4 ld_el(const float* p, uint64_t pol) {
    float4 v;
    asm volatile("ld.global.nc.L2::cache_hint.v4.f32 {%0,%1,%2,%3}, [%4], %5;"
                 : "=f"(v.x), "=f"(v.y), "=f"(v.z), "=f"(v.w) : "l"(p), "l"(pol));
    return v;
}

__device__ __forceinline__ void mma_bf16(float d[4], const uint32_t a[4], const uint32_t b[2]) {
    asm volatile(
        "mma.sync.aligned.m16n8k16.row.col.f32.bf16.bf16.f32 "
        "{%0,%1,%2,%3}, {%4,%5,%6,%7}, {%8,%9}, {%0,%1,%2,%3};\n"
        : "+f"(d[0]), "+f"(d[1]), "+f"(d[2]), "+f"(d[3])
        : "r"(a[0]), "r"(a[1]), "r"(a[2]), "r"(a[3]), "r"(b[0]), "r"(b[1]));
}

// ---------------- merged setup: weights, bias, bounds, Z init -----------------
__global__ void k_setup(const float* __restrict__ W_ih, const float* __restrict__ W_hh,
                        const float* __restrict__ b_ih, const float* __restrict__ b_hh,
                        const int* __restrict__ batch, const float* __restrict__ qstar,
                        int n) {
    int idx = blockIdx.x * blockDim.x + threadIdx.x;
    const int RW1 = GDIM * KB1;
    const int RW2 = RW1 + GDIM * KB2;
    const int RB  = RW2 + GDIM;
    const int RS  = RB + n;
    const int RZ1 = RS + NB * KB1;
    const int RC  = RZ1 + NB * NF;
    const int RZ2 = RC + NB * 144;
    if (idx < RW1) {
        int jp = idx / KB1, u = idx % KB1;
        int j = (jp & 3) * 200 + (jp >> 2);
        int s = u / SEC1, k = u % SEC1;
        float a = 0.f;
        if (k < 400)      a = W_ih[j * 400 + k];
        else if (k < 600) a = W_hh[j * 200 + (k - 400)];
        __nv_bfloat16 hi = __float2bfloat16(a);
        g_Wb1[idx] = (s < 2) ? hi : __float2bfloat16(a - __bfloat162float(hi));
    } else if (idx < RW2) {
        int t = idx - RW1;
        int jp = t / KB2, u = t % KB2;
        int j = (jp & 3) * 200 + (jp >> 2);
        int s = u / SEC2, k = u % SEC2;
        float a = 0.f;
        if (k < 400) {
            a = W_ih[j * 400 + k];
            if (k < 200) a += W_hh[j * 200 + k];
        }
        __nv_bfloat16 hi = __float2bfloat16(a);
        g_Wb2[t] = (s < 2) ? hi : __float2bfloat16(a - __bfloat162float(hi));
    } else if (idx < RB) {
        int jp = idx - RW2;
        int j = (jp & 3) * 200 + (jp >> 2);
        g_biasP[jp] = b_ih[j] + b_hh[j];
    } else if (idx < RS) {
        int i = idx - RB;
        int b = batch[i];
        if (i == 0) { for (int q = 0; q <= b; ++q) g_seg[q] = 0; }
        else {
            int pb = batch[i - 1];
            for (int q = pb + 1; q <= b; ++q) g_seg[q] = i;
        }
        if (i == n - 1) { for (int q = b + 1; q <= NB; ++q) g_seg[q] = n; }
    } else if (idx < RZ1) {
        int t = idx - RS;
        int b = t / KB1, u = t % KB1;
        int s = u / SEC1, k = u % SEC1;
        if (k < 400) {
            float v = qstar[b * 400 + k];
            __nv_bfloat16 hi = __float2bfloat16(v);
            g_Zb1[t] = (s == 1) ? __float2bfloat16(v - __bfloat162float(hi)) : hi;
        } else if (k >= 600) {
            g_Zb1[t] = __float2bfloat16(0.f);
        }
    } else if (idx < RC) {
        g_C[idx - RZ1] = 0.f;
    } else if (idx < RZ2) {
        int t = idx - RC;
        int b = t / 144, k = t % 144;
        int sec = k / 48;
        g_Zb2[b * KB2 + sec * SEC2 + 400 + (k % 48)] = __float2bfloat16(0.f);
    }
}

// ---------------- h0 = segment_sum(cos*x) → Zb1 h sections --------------------
__global__ void __launch_bounds__(256) k_h0(const float* __restrict__ x,
                                            const float* __restrict__ cosc) {
    __shared__ float part[8][NF];
    int b = blockIdx.x;
    int s0 = g_seg[b], s1 = g_seg[b + 1];
    int tid = threadIdx.x, lane = tid & 31, wid = tid >> 5;
    uint64_t pol = mk_policy();

    float4 aA = make_float4(0.f, 0.f, 0.f, 0.f);
    float4 aB = make_float4(0.f, 0.f, 0.f, 0.f);
    for (int n = s0 + wid; n < s1; n += 8) {
        float c = __ldg(cosc + n);
        const float* rp = x + (size_t)n * NF;
        float4 v = ld_el(rp + 4 * lane, pol);
        aA.x += c * v.x; aA.y += c * v.y; aA.z += c * v.z; aA.w += c * v.w;
        if (lane < 18) {
            float4 v2 = ld_el(rp + 128 + 4 * lane, pol);
            aB.x += c * v2.x; aB.y += c * v2.y; aB.z += c * v2.z; aB.w += c * v2.w;
        }
    }
    part[wid][4 * lane + 0] = aA.x; part[wid][4 * lane + 1] = aA.y;
    part[wid][4 * lane + 2] = aA.z; part[wid][4 * lane + 3] = aA.w;
    if (lane < 18) {
        part[wid][128 + 4 * lane + 0] = aB.x; part[wid][128 + 4 * lane + 1] = aB.y;
        part[wid][128 + 4 * lane + 2] = aB.z; part[wid][128 + 4 * lane + 3] = aB.w;
    }
    __syncthreads();
    if (tid < NF) {
        float s = 0.f;
#pragma unroll
        for (int w = 0; w < 8; ++w) s += part[w][tid];
        __nv_bfloat16 hi = __float2bfloat16(s);
        __nv_bfloat16 lo = __float2bfloat16(s - __bfloat162float(hi));
        size_t base = (size_t)b * KB1;
        g_Zb1[base + 400 + tid] = hi;
        g_Zb1[base + SEC1 + 400 + tid] = lo;
        g_Zb1[base + 2 * SEC1 + 400 + tid] = hi;
    }
}

// -------- split-K mma.sync bf16 GEMM (CTA 128x80, 4 K-splits) ------------------
template<int KB, int NCHUNK>
__global__ void __launch_bounds__(256, 2) k_gemm_split(const __nv_bfloat16* __restrict__ A,
                                                       const __nv_bfloat16* __restrict__ Wb) {
    extern __shared__ char smem[];
    uint32_t sbase = smem_u32(smem);
    int tid = threadIdx.x, lane = tid & 31, warp = tid >> 5;
    int m0 = blockIdx.x * GM;
    int n0 = blockIdx.y * GNT;
    int z  = blockIdx.z;
    int c0 = (z * NCHUNK) / NSPLIT, c1 = ((z + 1) * NCHUNK) / NSPLIT;

    int wm = warp >> 1, wn = warp & 1;
    int r7 = lane & 7, quad = lane >> 3;
    int gg = lane >> 2, t4 = lane & 3;

    float acc[2][5][4];
#pragma unroll
    for (int t = 0; t < 2; ++t)
#pragma unroll
        for (int u = 0; u < 5; ++u)
#pragma unroll
            for (int v = 0; v < 4; ++v) acc[t][u][v] = 0.f;

    auto load_chunk = [&](int c) {
        int s = (c - c0) % NSTAGE;
        uint32_t aBase = sbase + SOFF + s * STG;
        uint32_t bBase = aBase + 16384;
        const __nv_bfloat16* gA = A + (size_t)m0 * KB + c * 64;
        const __nv_bfloat16* gW = Wb + (size_t)n0 * KB + c * 64;
#pragma unroll
        for (int i = 0; i < 4; ++i) {
            int t = tid + i * 256;
            int r = t >> 3, v = t & 7;
            uint32_t bo = (uint32_t)r * 128 + v * 16;
            cp16(aBase + (bo ^ ((r & 7) << 4)), gA + (size_t)r * KB + v * 8);
        }
        for (int t = tid; t < 80 * 8; t += 256) {
            int r = t >> 3, v = t & 7;
            uint32_t bo = (uint32_t)r * 128 + v * 16;
            cp16(bBase + (bo ^ ((r & 7) << 4)), gW + (size_t)r * KB + v * 8);
        }
        CP_COMMIT();
    };

    auto compute = [&](int slot) {
        uint32_t aB = sbase + SOFF + slot * STG;
        uint32_t bB = aB + 16384;
#pragma unroll
        for (int k16 = 0; k16 < 4; ++k16) {
            int kb = k16 * 32;
            uint32_t aF[2][4], bF[5][2];
#pragma unroll
            for (int t = 0; t < 2; ++t) {
                int row = wm * 32 + t * 16 + (quad & 1) * 8 + r7;
                int cb = kb + (quad >> 1) * 16;
                uint32_t ad = aB + (((uint32_t)row * 128 + cb) ^ ((row & 7) << 4));
                asm volatile("ldmatrix.sync.aligned.m8n8.x4.shared.b16 {%0,%1,%2,%3}, [%4];"
                             : "=r"(aF[t][0]), "=r"(aF[t][1]), "=r"(aF[t][2]), "=r"(aF[t][3])
                             : "r"(ad));
            }
#pragma unroll
            for (int p = 0; p < 2; ++p) {
                int row = wn * 40 + (2 * p + (quad >> 1)) * 8 + r7;
                int cb = kb + (quad & 1) * 16;
                uint32_t bd = bB + (((uint32_t)row * 128 + cb) ^ ((row & 7) << 4));
                asm volatile("ldmatrix.sync.aligned.m8n8.x4.shared.b16 {%0,%1,%2,%3}, [%4];"
                             : "=r"(bF[2 * p][0]), "=r"(bF[2 * p][1]),
                               "=r"(bF[2 * p + 1][0]), "=r"(bF[2 * p + 1][1])
                             : "r"(bd));
            }
            {
                int row = wn * 40 + 32 + r7;
                int cb = kb + (quad & 1) * 16;
                uint32_t bd = bB + (((uint32_t)row * 128 + cb) ^ ((row & 7) << 4));
                asm volatile("ldmatrix.sync.aligned.m8n8.x2.shared.b16 {%0,%1}, [%2];"
                             : "=r"(bF[4][0]), "=r"(bF[4][1]) : "r"(bd));
            }
#pragma unroll
            for (int t = 0; t < 2; ++t)
#pragma unroll
                for (int u = 0; u < 5; ++u) mma_bf16(acc[t][u], aF[t], bF[u]);
        }
    };

    load_chunk(c0);
    if (c0 + 1 < c1) load_chunk(c0 + 1);
    for (int c = c0; c < c1; ++c) {
        if (c + 1 < c1) asm volatile("cp.async.wait_group 1;" ::: "memory");
        else            asm volatile("cp.async.wait_group 0;" ::: "memory");
        __syncthreads();
        if (c + 2 < c1) load_chunk(c + 2);
        compute((c - c0) % NSTAGE);
    }

    // write partials
    float* Gp = g_Gp + (size_t)z * NB * GDIM;
#pragma unroll
    for (int t = 0; t < 2; ++t)
#pragma unroll
        for (int u = 0; u < 5; ++u) {
            int row = m0 + wm * 32 + t * 16 + gg;
            int col = n0 + wn * 40 + u * 8 + 2 * t4;
            *(float2*)(Gp + (size_t)row * GDIM + col)       = make_float2(acc[t][u][0], acc[t][u][1]);
            *(float2*)(Gp + (size_t)(row + 8) * GDIM + col) = make_float2(acc[t][u][2], acc[t][u][3]);
        }
}

// ---------------- epilogue: sum partials + LSTM pointwise ----------------------
__global__ void k_pointE() {
    int idx = blockIdx.x * blockDim.x + threadIdx.x;
    if (idx >= NB * NF) return;
    int b = idx / NF, u = idx % NF;
    const float* p0 = g_Gp + (size_t)b * GDIM + 4 * u;
    float4 s = *(const float4*)p0;
#pragma unroll
    for (int z = 1; z < NSPLIT; ++z) {
        float4 t = *(const float4*)(p0 + (size_t)z * NB * GDIM);
        s.x += t.x; s.y += t.y; s.z += t.z; s.w += t.w;
    }
    const float4 bb = *(const float4*)(g_biasP + 4 * u);
    float i_ = s.x + bb.x;
    float f_ = s.y + bb.y;
    float g_ = s.z + bb.z;
    float o_ = s.w + bb.w;
    float c = g_C[(size_t)b * NF + u];
    c = sigmoidf_(f_) * c + sigmoidf_(i_) * tanhf(g_);
    float h = sigmoidf_(o_) * tanhf(c);
    g_C[(size_t)b * NF + u] = c;
    g_Z[(size_t)b * NF + u] = h;
    __nv_bfloat16 hi = __float2bfloat16(h);
    __nv_bfloat16 lo = __float2bfloat16(h - __bfloat162float(hi));
    __nv_bfloat16* Zr = g_Zb2 + (size_t)b * KB2;
    Zr[u] = hi; Zr[SEC2 + u] = lo; Zr[2 * SEC2 + u] = hi;
}

// ------ fused single-pass (online softmax) per-segment attention ---------------
__global__ void __launch_bounds__(256) k_attn(const float* __restrict__ x,
                                              float* __restrict__ out, int writeOut) {
    __shared__ float qs[208];
    __shared__ float part[8][NF];
    __shared__ float pm[8], ps[8], fac[8];

    int b = blockIdx.x;
    int s0 = g_seg[b], s1 = g_seg[b + 1];
    int tid = threadIdx.x, lane = tid & 31, wid = tid >> 5;
    uint64_t pol = mk_policy();

    if (tid < NF) qs[tid] = g_Z[b * NF + tid];
    __syncthreads();

    const float4* q4 = (const float4*)qs;
    float4 qa = q4[lane];
    float4 qb = make_float4(0.f, 0.f, 0.f, 0.f);
    if (lane < 18) qb = q4[32 + lane];

    float4 ra = make_float4(0.f, 0.f, 0.f, 0.f);
    float4 rb = make_float4(0.f, 0.f, 0.f, 0.f);
    float run_m = -3.0e38f, run_s = 0.f;

    for (int n = s0 + wid; n < s1; n += 8) {
        const float* rp = x + (size_t)n * NF;
        float4 va = ld_el(rp + 4 * lane, pol);
        float4 vb = make_float4(0.f, 0.f, 0.f, 0.f);
        float p = va.x * qa.x + va.y * qa.y + va.z * qa.z + va.w * qa.w;
        if (lane < 18) {
            vb = ld_el(rp + 128 + 4 * lane, pol);
            p += vb.x * qb.x + vb.y * qb.y + vb.z * qb.z + vb.w * qb.w;
        }
#pragma unroll
        for (int o = 16; o > 0; o >>= 1) p += __shfl_xor_sync(0xffffffffu, p, o);
        if (p > run_m) {
            float sc = __expf(run_m - p);
            ra.x *= sc; ra.y *= sc; ra.z *= sc; ra.w *= sc;
            rb.x *= sc; rb.y *= sc; rb.z *= sc; rb.w *= sc;
            run_s *= sc;
            run_m = p;
        }
        float w = __expf(p - run_m);
        run_s += w;
        ra.x += w * va.x; ra.y += w * va.y; ra.z += w * va.z; ra.w += w * va.w;
        rb.x += w * vb.x; rb.y += w * vb.y; rb.z += w * vb.z; rb.w += w * vb.w;
    }

    part[wid][4 * lane + 0] = ra.x; part[wid][4 * lane + 1] = ra.y;
    part[wid][4 * lane + 2] = ra.z; part[wid][4 * lane + 3] = ra.w;
    if (lane < 18) {
        part[wid][128 + 4 * lane + 0] = rb.x; part[wid][128 + 4 * lane + 1] = rb.y;
        part[wid][128 + 4 * lane + 2] = rb.z; part[wid][128 + 4 * lane + 3] = rb.w;
    }
    if (lane == 0) { pm[wid] = run_m; ps[wid] = run_s; }
    __syncthreads();

    if (tid < 8) {
        float M = pm[0];
#pragma unroll
        for (int w = 1; w < 8; ++w) M = fmaxf(M, pm[w]);
        fac[tid] = __expf(pm[tid] - M);
    }
    __syncthreads();

    if (tid < NF) {
        float denom = 0.f, r = 0.f;
#pragma unroll
        for (int w = 0; w < 8; ++w) {
            denom += fac[w] * ps[w];
            r     += fac[w] * part[w][tid];
        }
        r = (denom > 0.f) ? (r / denom) : 0.f;
        __nv_bfloat16 hi = __float2bfloat16(r);
        __nv_bfloat16 lo = __float2bfloat16(r - __bfloat162float(hi));
        size_t base = (size_t)b * KB2 + 200 + tid;
        g_Zb2[base] = hi;
        g_Zb2[base + SEC2] = lo;
        g_Zb2[base + 2 * SEC2] = hi;
        if (writeOut) {
            out[b * 400 + tid] = qs[tid];
            out[b * 400 + 200 + tid] = r;
        }
    }
}

// ---------------- launch ---------------------------------------------------------
extern "C" void kernel_launch(void* const* d_in, const int* in_sizes, int n_in,
                              void* d_out, int out_size) {
    const float* x     = (const float*)d_in[0];
    const int*   batch = (const int*)  d_in[1];
    const float* cosc  = (const float*)d_in[2];
    const float* qstar = (const float*)d_in[3];
    const float* W_ih  = (const float*)d_in[4];
    const float* W_hh  = (const float*)d_in[5];
    const float* b_ih  = (const float*)d_in[6];
    const float* b_hh  = (const float*)d_in[7];
    float* out = (float*)d_out;

    int n = in_sizes[1];

    const int smemBytes = SOFF + NSTAGE * STG;   // 80896
    cudaFuncSetAttribute(k_gemm_split<KB1, NCH1>,
                         cudaFuncAttributeMaxDynamicSharedMemorySize, smemBytes);
    cudaFuncSetAttribute(k_gemm_split<KB2, NCH2>,
                         cudaFuncAttributeMaxDynamicSharedMemorySize, smemBytes);

    __nv_bfloat16 *zb1, *zb2, *wb1, *wb2;
    cudaGetSymbolAddress((void**)&zb1, g_Zb1);
    cudaGetSymbolAddress((void**)&zb2, g_Zb2);
    cudaGetSymbolAddress((void**)&wb1, g_Wb1);
    cudaGetSymbolAddress((void**)&wb2, g_Wb2);

    const int setupTot = GDIM * KB1 + GDIM * KB2 + GDIM + n + NB * KB1 + NB * NF + NB * 144;
    k_setup<<<(setupTot + 255) / 256, 256>>>(W_ih, W_hh, b_ih, b_hh, batch, qstar, n);
    k_h0   <<<NB, 256>>>(x, cosc);

    dim3 ggrid(NB / GM, GDIM / GNT, NSPLIT);     // 16 x 10 x 4 = 640 CTAs
    for (int s = 0; s < STEPS; ++s) {
        if (s == 0) k_gemm_split<KB1, NCH1><<<ggrid, 256, smemBytes>>>(zb1, wb1);
        else        k_gemm_split<KB2, NCH2><<<ggrid, 256, smemBytes>>>(zb2, wb2);
        k_pointE<<<(NB * NF + 255) / 256, 256>>>();
        k_attn  <<<NB, 256>>>(x, out, s == STEPS - 1 ? 1 : 0);
    }
}

// round 8
// speedup vs baseline: 2.0776x; 1.0376x over previous
#include <cuda_runtime.h>
#include <cuda_bf16.h>
#include <cstdint>

// Problem constants
#define NTOT 131072
#define NB   2048
#define NF   200
#define GDIM 800
#define STEPS 3

// bf16x3 via K-concatenation (plain bf16 GEMM)
#define KB1 1920
#define KB2 1344
#define SEC1 640
#define SEC2 448
#define NCH1 30          // K chunks of 64
#define NCH2 21
#define GM 128
#define GNT 80
#define NSPLIT 5
#define NSTAGE 3
#define STG 26624        // A 128x64 bf16 (16384) + B 80x64 bf16 (10240)
#define SOFF 1024

// ---------------- scratch ----------------------------------------------------
__device__ __nv_bfloat16 g_Zb1[NB * KB1];
__device__ __nv_bfloat16 g_Zb2[NB * KB2];
__device__ __nv_bfloat16 g_Wb1[GDIM * KB1];   // permuted rows jp = unit*4+gate
__device__ __nv_bfloat16 g_Wb2[GDIM * KB2];
__device__ float g_biasP[GDIM];
__device__ float g_C[NB * NF];                // LSTM cell state
__device__ float g_Gp[NSPLIT * NB * GDIM];    // split-K partials
__device__ int   g_seg[NB + 2];

// ---------------- helpers ----------------------------------------------------
__device__ __forceinline__ uint32_t smem_u32(const void* p) {
    return (uint32_t)__cvta_generic_to_shared(p);
}
__device__ __forceinline__ float sigmoidf_(float x) { return 1.0f / (1.0f + expf(-x)); }

__device__ __forceinline__ void cp16(uint32_t dst, const void* src) {
    asm volatile("cp.async.cg.shared.global [%0], [%1], 16;" :: "r"(dst), "l"(src) : "memory");
}
#define CP_COMMIT() asm volatile("cp.async.commit_group;" ::: "memory")

// x loads: keep resident in L2 across passes (cache-hint policy form)
__device__ __forceinline__ uint64_t mk_policy() {
    uint64_t pol;
    asm volatile("createpolicy.fractional.L2::evict_last.b64 %0, 1.0;" : "=l"(pol));
    return pol;
}
__device__ __forceinline__ float4 ld_el(const float* p, uint64_t pol) {
    float4 v;
    asm volatile("ld.global.nc.L2::cache_hint.v4.f32 {%0,%1,%2,%3}, [%4], %5;"
                 : "=f"(v.x), "=f"(v.y), "=f"(v.z), "=f"(v.w) : "l"(p), "l"(pol));
    return v;
}

__device__ __forceinline__ void mma_bf16(float d[4], const uint32_t a[4], const uint32_t b[2]) {
    asm volatile(
        "mma.sync.aligned.m16n8k16.row.col.f32.bf16.bf16.f32 "
        "{%0,%1,%2,%3}, {%4,%5,%6,%7}, {%8,%9}, {%0,%1,%2,%3};\n"
        : "+f"(d[0]), "+f"(d[1]), "+f"(d[2]), "+f"(d[3])
        : "r"(a[0]), "r"(a[1]), "r"(a[2]), "r"(a[3]), "r"(b[0]), "r"(b[1]));
}

// ---------------- merged setup: weights, bias, bounds, Z init -----------------
__global__ void k_setup(const float* __restrict__ W_ih, const float* __restrict__ W_hh,
                        const float* __restrict__ b_ih, const float* __restrict__ b_hh,
                        const int* __restrict__ batch, const float* __restrict__ qstar,
                        int n) {
    int idx = blockIdx.x * blockDim.x + threadIdx.x;
    const int RW1 = GDIM * KB1;
    const int RW2 = RW1 + GDIM * KB2;
    const int RB  = RW2 + GDIM;
    const int RS  = RB + n;
    const int RZ1 = RS + NB * KB1;
    const int RC  = RZ1 + NB * NF;
    const int RZ2 = RC + NB * 144;
    if (idx < RW1) {
        int jp = idx / KB1, u = idx % KB1;
        int j = (jp & 3) * 200 + (jp >> 2);
        int s = u / SEC1, k = u % SEC1;
        float a = 0.f;
        if (k < 400)      a = W_ih[j * 400 + k];
        else if (k < 600) a = W_hh[j * 200 + (k - 400)];
        __nv_bfloat16 hi = __float2bfloat16(a);
        g_Wb1[idx] = (s < 2) ? hi : __float2bfloat16(a - __bfloat162float(hi));
    } else if (idx < RW2) {
        int t = idx - RW1;
        int jp = t / KB2, u = t % KB2;
        int j = (jp & 3) * 200 + (jp >> 2);
        int s = u / SEC2, k = u % SEC2;
        float a = 0.f;
        if (k < 400) {
            a = W_ih[j * 400 + k];
            if (k < 200) a += W_hh[j * 200 + k];
        }
        __nv_bfloat16 hi = __float2bfloat16(a);
        g_Wb2[t] = (s < 2) ? hi : __float2bfloat16(a - __bfloat162float(hi));
    } else if (idx < RB) {
        int jp = idx - RW2;
        int j = (jp & 3) * 200 + (jp >> 2);
        g_biasP[jp] = b_ih[j] + b_hh[j];
    } else if (idx < RS) {
        int i = idx - RB;
        int b = batch[i];
        if (i == 0) { for (int q = 0; q <= b; ++q) g_seg[q] = 0; }
        else {
            int pb = batch[i - 1];
            for (int q = pb + 1; q <= b; ++q) g_seg[q] = i;
        }
        if (i == n - 1) { for (int q = b + 1; q <= NB; ++q) g_seg[q] = n; }
    } else if (idx < RZ1) {
        int t = idx - RS;
        int b = t / KB1, u = t % KB1;
        int s = u / SEC1, k = u % SEC1;
        if (k < 400) {
            float v = qstar[b * 400 + k];
            __nv_bfloat16 hi = __float2bfloat16(v);
            g_Zb1[t] = (s == 1) ? __float2bfloat16(v - __bfloat162float(hi)) : hi;
        } else if (k >= 600) {
            g_Zb1[t] = __float2bfloat16(0.f);
        }
    } else if (idx < RC) {
        g_C[idx - RZ1] = 0.f;
    } else if (idx < RZ2) {
        int t = idx - RC;
        int b = t / 144, k = t % 144;
        int sec = k / 48;
        g_Zb2[b * KB2 + sec * SEC2 + 400 + (k % 48)] = __float2bfloat16(0.f);
    }
}

// ---------------- h0 = segment_sum(cos*x) → Zb1 h sections --------------------
__global__ void __launch_bounds__(256) k_h0(const float* __restrict__ x,
                                            const float* __restrict__ cosc) {
    __shared__ float part[8][NF];
    int b = blockIdx.x;
    int s0 = g_seg[b], s1 = g_seg[b + 1];
    int tid = threadIdx.x, lane = tid & 31, wid = tid >> 5;
    uint64_t pol = mk_policy();

    float4 aA = make_float4(0.f, 0.f, 0.f, 0.f);
    float4 aB = make_float4(0.f, 0.f, 0.f, 0.f);
    for (int n = s0 + wid; n < s1; n += 8) {
        float c = __ldg(cosc + n);
        const float* rp = x + (size_t)n * NF;
        float4 v = ld_el(rp + 4 * lane, pol);
        aA.x += c * v.x; aA.y += c * v.y; aA.z += c * v.z; aA.w += c * v.w;
        if (lane < 18) {
            float4 v2 = ld_el(rp + 128 + 4 * lane, pol);
            aB.x += c * v2.x; aB.y += c * v2.y; aB.z += c * v2.z; aB.w += c * v2.w;
        }
    }
    part[wid][4 * lane + 0] = aA.x; part[wid][4 * lane + 1] = aA.y;
    part[wid][4 * lane + 2] = aA.z; part[wid][4 * lane + 3] = aA.w;
    if (lane < 18) {
        part[wid][128 + 4 * lane + 0] = aB.x; part[wid][128 + 4 * lane + 1] = aB.y;
        part[wid][128 + 4 * lane + 2] = aB.z; part[wid][128 + 4 * lane + 3] = aB.w;
    }
    __syncthreads();
    if (tid < NF) {
        float s = 0.f;
#pragma unroll
        for (int w = 0; w < 8; ++w) s += part[w][tid];
        __nv_bfloat16 hi = __float2bfloat16(s);
        __nv_bfloat16 lo = __float2bfloat16(s - __bfloat162float(hi));
        size_t base = (size_t)b * KB1;
        g_Zb1[base + 400 + tid] = hi;
        g_Zb1[base + SEC1 + 400 + tid] = lo;
        g_Zb1[base + 2 * SEC1 + 400 + tid] = hi;
    }
}

// -------- split-K mma.sync bf16 GEMM (CTA 128x80, 5 K-splits) ------------------
template<int KB, int NCHUNK>
__global__ void __launch_bounds__(256, 2) k_gemm_split(const __nv_bfloat16* __restrict__ A,
                                                       const __nv_bfloat16* __restrict__ Wb) {
    extern __shared__ char smem[];
    uint32_t sbase = smem_u32(smem);
    int tid = threadIdx.x, lane = tid & 31, warp = tid >> 5;
    int m0 = blockIdx.x * GM;
    int n0 = blockIdx.y * GNT;
    int z  = blockIdx.z;
    int c0 = (z * NCHUNK) / NSPLIT, c1 = ((z + 1) * NCHUNK) / NSPLIT;

    int wm = warp >> 1, wn = warp & 1;
    int r7 = lane & 7, quad = lane >> 3;
    int gg = lane >> 2, t4 = lane & 3;

    float acc[2][5][4];
#pragma unroll
    for (int t = 0; t < 2; ++t)
#pragma unroll
        for (int u = 0; u < 5; ++u)
#pragma unroll
            for (int v = 0; v < 4; ++v) acc[t][u][v] = 0.f;

    auto load_chunk = [&](int c) {
        int s = (c - c0) % NSTAGE;
        uint32_t aBase = sbase + SOFF + s * STG;
        uint32_t bBase = aBase + 16384;
        const __nv_bfloat16* gA = A + (size_t)m0 * KB + c * 64;
        const __nv_bfloat16* gW = Wb + (size_t)n0 * KB + c * 64;
#pragma unroll
        for (int i = 0; i < 4; ++i) {
            int t = tid + i * 256;
            int r = t >> 3, v = t & 7;
            uint32_t bo = (uint32_t)r * 128 + v * 16;
            cp16(aBase + (bo ^ ((r & 7) << 4)), gA + (size_t)r * KB + v * 8);
        }
        for (int t = tid; t < 80 * 8; t += 256) {
            int r = t >> 3, v = t & 7;
            uint32_t bo = (uint32_t)r * 128 + v * 16;
            cp16(bBase + (bo ^ ((r & 7) << 4)), gW + (size_t)r * KB + v * 8);
        }
        CP_COMMIT();
    };

    auto compute = [&](int slot) {
        uint32_t aB = sbase + SOFF + slot * STG;
        uint32_t bB = aB + 16384;
#pragma unroll
        for (int k16 = 0; k16 < 4; ++k16) {
            int kb = k16 * 32;
            uint32_t aF[2][4], bF[5][2];
#pragma unroll
            for (int t = 0; t < 2; ++t) {
                int row = wm * 32 + t * 16 + (quad & 1) * 8 + r7;
                int cb = kb + (quad >> 1) * 16;
                uint32_t ad = aB + (((uint32_t)row * 128 + cb) ^ ((row & 7) << 4));
                asm volatile("ldmatrix.sync.aligned.m8n8.x4.shared.b16 {%0,%1,%2,%3}, [%4];"
                             : "=r"(aF[t][0]), "=r"(aF[t][1]), "=r"(aF[t][2]), "=r"(aF[t][3])
                             : "r"(ad));
            }
#pragma unroll
            for (int p = 0; p < 2; ++p) {
                int row = wn * 40 + (2 * p + (quad >> 1)) * 8 + r7;
                int cb = kb + (quad & 1) * 16;
                uint32_t bd = bB + (((uint32_t)row * 128 + cb) ^ ((row & 7) << 4));
                asm volatile("ldmatrix.sync.aligned.m8n8.x4.shared.b16 {%0,%1,%2,%3}, [%4];"
                             : "=r"(bF[2 * p][0]), "=r"(bF[2 * p][1]),
                               "=r"(bF[2 * p + 1][0]), "=r"(bF[2 * p + 1][1])
                             : "r"(bd));
            }
            {
                int row = wn * 40 + 32 + r7;
                int cb = kb + (quad & 1) * 16;
                uint32_t bd = bB + (((uint32_t)row * 128 + cb) ^ ((row & 7) << 4));
                asm volatile("ldmatrix.sync.aligned.m8n8.x2.shared.b16 {%0,%1}, [%2];"
                             : "=r"(bF[4][0]), "=r"(bF[4][1]) : "r"(bd));
            }
#pragma unroll
            for (int t = 0; t < 2; ++t)
#pragma unroll
                for (int u = 0; u < 5; ++u) mma_bf16(acc[t][u], aF[t], bF[u]);
        }
    };

    load_chunk(c0);
    if (c0 + 1 < c1) load_chunk(c0 + 1);
    for (int c = c0; c < c1; ++c) {
        if (c + 1 < c1) asm volatile("cp.async.wait_group 1;" ::: "memory");
        else            asm volatile("cp.async.wait_group 0;" ::: "memory");
        __syncthreads();
        if (c + 2 < c1) load_chunk(c + 2);
        compute((c - c0) % NSTAGE);
    }

    // write partials
    float* Gp = g_Gp + (size_t)z * NB * GDIM;
#pragma unroll
    for (int t = 0; t < 2; ++t)
#pragma unroll
        for (int u = 0; u < 5; ++u) {
            int row = m0 + wm * 32 + t * 16 + gg;
            int col = n0 + wn * 40 + u * 8 + 2 * t4;
            *(float2*)(Gp + (size_t)row * GDIM + col)       = make_float2(acc[t][u][0], acc[t][u][1]);
            *(float2*)(Gp + (size_t)(row + 8) * GDIM + col) = make_float2(acc[t][u][2], acc[t][u][3]);
        }
}

// --- fused: split-K reduce + LSTM pointwise (prologue) + online-softmax attn ---
__global__ void __launch_bounds__(256) k_attn(const float* __restrict__ x,
                                              float* __restrict__ out, int writeOut) {
    __shared__ float qs[208];
    __shared__ float part[8][NF];
    __shared__ float pm[8], ps[8], fac[8];

    int b = blockIdx.x;
    int s0 = g_seg[b], s1 = g_seg[b + 1];
    int tid = threadIdx.x, lane = tid & 31, wid = tid >> 5;
    uint64_t pol = mk_policy();

    // ---- prologue: sum 5 split-K partials, LSTM pointwise → q (row b) --------
    if (tid < NF) {
        const float* p0 = g_Gp + (size_t)b * GDIM + 4 * tid;
        float4 s = *(const float4*)p0;
#pragma unroll
        for (int z = 1; z < NSPLIT; ++z) {
            float4 t = *(const float4*)(p0 + (size_t)z * NB * GDIM);
            s.x += t.x; s.y += t.y; s.z += t.z; s.w += t.w;
        }
        const float4 bb = *(const float4*)(g_biasP + 4 * tid);
        float i_ = s.x + bb.x;
        float f_ = s.y + bb.y;
        float g_ = s.z + bb.z;
        float o_ = s.w + bb.w;
        float c = g_C[(size_t)b * NF + tid];
        c = sigmoidf_(f_) * c + sigmoidf_(i_) * tanhf(g_);
        float h = sigmoidf_(o_) * tanhf(c);
        g_C[(size_t)b * NF + tid] = c;
        qs[tid] = h;
        __nv_bfloat16 hi = __float2bfloat16(h);
        __nv_bfloat16 lo = __float2bfloat16(h - __bfloat162float(hi));
        __nv_bfloat16* Zr = g_Zb2 + (size_t)b * KB2;
        Zr[tid] = hi; Zr[SEC2 + tid] = lo; Zr[2 * SEC2 + tid] = hi;
    }
    __syncthreads();

    const float4* q4 = (const float4*)qs;
    float4 qa = q4[lane];
    float4 qb = make_float4(0.f, 0.f, 0.f, 0.f);
    if (lane < 18) qb = q4[32 + lane];

    float4 ra = make_float4(0.f, 0.f, 0.f, 0.f);
    float4 rb = make_float4(0.f, 0.f, 0.f, 0.f);
    float run_m = -3.0e38f, run_s = 0.f;

    // streaming loop: two rows per iteration per warp for ILP
    for (int n = s0 + wid; n < s1; n += 16) {
        int n2 = n + 8;
        bool has2 = (n2 < s1);
        const float* rp = x + (size_t)n * NF;
        float4 va = ld_el(rp + 4 * lane, pol);
        float4 vb = make_float4(0.f, 0.f, 0.f, 0.f);
        float4 wa = make_float4(0.f, 0.f, 0.f, 0.f);
        float4 wb = make_float4(0.f, 0.f, 0.f, 0.f);
        if (has2) {
            const float* rp2 = x + (size_t)n2 * NF;
            wa = ld_el(rp2 + 4 * lane, pol);
            if (lane < 18) wb = ld_el(rp2 + 128 + 4 * lane, pol);
        }
        float p = va.x * qa.x + va.y * qa.y + va.z * qa.z + va.w * qa.w;
        float p2 = wa.x * qa.x + wa.y * qa.y + wa.z * qa.z + wa.w * qa.w;
        if (lane < 18) {
            vb = ld_el(rp + 128 + 4 * lane, pol);
            p += vb.x * qb.x + vb.y * qb.y + vb.z * qb.z + vb.w * qb.w;
            p2 += wb.x * qb.x + wb.y * qb.y + wb.z * qb.z + wb.w * qb.w;
        }
#pragma unroll
        for (int o = 16; o > 0; o >>= 1) {
            p  += __shfl_xor_sync(0xffffffffu, p, o);
            p2 += __shfl_xor_sync(0xffffffffu, p2, o);
        }
        // online update row n
        if (p > run_m) {
            float sc = __expf(run_m - p);
            ra.x *= sc; ra.y *= sc; ra.z *= sc; ra.w *= sc;
            rb.x *= sc; rb.y *= sc; rb.z *= sc; rb.w *= sc;
            run_s *= sc;
            run_m = p;
        }
        float w = __expf(p - run_m);
        run_s += w;
        ra.x += w * va.x; ra.y += w * va.y; ra.z += w * va.z; ra.w += w * va.w;
        rb.x += w * vb.x; rb.y += w * vb.y; rb.z += w * vb.z; rb.w += w * vb.w;
        // online update row n+8
        if (has2) {
            if (p2 > run_m) {
                float sc = __expf(run_m - p2);
                ra.x *= sc; ra.y *= sc; ra.z *= sc; ra.w *= sc;
                rb.x *= sc; rb.y *= sc; rb.z *= sc; rb.w *= sc;
                run_s *= sc;
                run_m = p2;
            }
            float w2 = __expf(p2 - run_m);
            run_s += w2;
            ra.x += w2 * wa.x; ra.y += w2 * wa.y; ra.z += w2 * wa.z; ra.w += w2 * wa.w;
            rb.x += w2 * wb.x; rb.y += w2 * wb.y; rb.z += w2 * wb.z; rb.w += w2 * wb.w;
        }
    }

    part[wid][4 * lane + 0] = ra.x; part[wid][4 * lane + 1] = ra.y;
    part[wid][4 * lane + 2] = ra.z; part[wid][4 * lane + 3] = ra.w;
    if (lane < 18) {
        part[wid][128 + 4 * lane + 0] = rb.x; part[wid][128 + 4 * lane + 1] = rb.y;
        part[wid][128 + 4 * lane + 2] = rb.z; part[wid][128 + 4 * lane + 3] = rb.w;
    }
    if (lane == 0) { pm[wid] = run_m; ps[wid] = run_s; }
    __syncthreads();

    if (tid < 8) {
        float M = pm[0];
#pragma unroll
        for (int w = 1; w < 8; ++w) M = fmaxf(M, pm[w]);
        fac[tid] = __expf(pm[tid] - M);
    }
    __syncthreads();

    if (tid < NF) {
        float denom = 0.f, r = 0.f;
#pragma unroll
        for (int w = 0; w < 8; ++w) {
            denom += fac[w] * ps[w];
            r     += fac[w] * part[w][tid];
        }
        r = (denom > 0.f) ? (r / denom) : 0.f;
        __nv_bfloat16 hi = __float2bfloat16(r);
        __nv_bfloat16 lo = __float2bfloat16(r - __bfloat162float(hi));
        size_t base = (size_t)b * KB2 + 200 + tid;
        g_Zb2[base] = hi;
        g_Zb2[base + SEC2] = lo;
        g_Zb2[base + 2 * SEC2] = hi;
        if (writeOut) {
            out[b * 400 + tid] = qs[tid];
            out[b * 400 + 200 + tid] = r;
        }
    }
}

// ---------------- launch ---------------------------------------------------------
extern "C" void kernel_launch(void* const* d_in, const int* in_sizes, int n_in,
                              void* d_out, int out_size) {
    const float* x     = (const float*)d_in[0];
    const int*   batch = (const int*)  d_in[1];
    const float* cosc  = (const float*)d_in[2];
    const float* qstar = (const float*)d_in[3];
    const float* W_ih  = (const float*)d_in[4];
    const float* W_hh  = (const float*)d_in[5];
    const float* b_ih  = (const float*)d_in[6];
    const float* b_hh  = (const float*)d_in[7];
    float* out = (float*)d_out;

    int n = in_sizes[1];

    const int smemBytes = SOFF + NSTAGE * STG;   // 80896
    cudaFuncSetAttribute(k_gemm_split<KB1, NCH1>,
                         cudaFuncAttributeMaxDynamicSharedMemorySize, smemBytes);
    cudaFuncSetAttribute(k_gemm_split<KB2, NCH2>,
                         cudaFuncAttributeMaxDynamicSharedMemorySize, smemBytes);

    __nv_bfloat16 *zb1, *zb2, *wb1, *wb2;
    cudaGetSymbolAddress((void**)&zb1, g_Zb1);
    cudaGetSymbolAddress((void**)&zb2, g_Zb2);
    cudaGetSymbolAddress((void**)&wb1, g_Wb1);
    cudaGetSymbolAddress((void**)&wb2, g_Wb2);

    const int setupTot = GDIM * KB1 + GDIM * KB2 + GDIM + n + NB * KB1 + NB * NF + NB * 144;
    k_setup<<<(setupTot + 255) / 256, 256>>>(W_ih, W_hh, b_ih, b_hh, batch, qstar, n);
    k_h0   <<<NB, 256>>>(x, cosc);

    dim3 ggrid(NB / GM, GDIM / GNT, NSPLIT);     // 16 x 10 x 5 = 800 CTAs
    for (int s = 0; s < STEPS; ++s) {
        if (s == 0) k_gemm_split<KB1, NCH1><<<ggrid, 256, smemBytes>>>(zb1, wb1);
        else        k_gemm_split<KB2, NCH2><<<ggrid, 256, smemBytes>>>(zb2, wb2);
        k_attn<<<NB, 256>>>(x, out, s == STEPS - 1 ? 1 : 0);
    }
}

// round 9
// speedup vs baseline: 2.0838x; 1.0030x over previous
#include <cuda_runtime.h>
#include <cuda_bf16.h>
#include <cstdint>

// Problem constants
#define NTOT 131072
#define NB   2048
#define NF   200
#define GDIM 800
#define STEPS 3

// bf16x3 via K-concatenation (plain bf16 GEMM)
#define KB1 1920
#define KB2 1344
#define SEC1 640
#define SEC2 448
#define NCH1 30          // K chunks of 64
#define NCH2 21
#define GM 128
#define GNT 80
#define NSPLIT 3
#define NSTAGE 2
#define STG 26624        // A 128x64 bf16 (16384) + B 80x64 bf16 (10240)
#define SOFF 1024

// ---------------- scratch ----------------------------------------------------
__device__ __nv_bfloat16 g_Zb1[NB * KB1];
__device__ __nv_bfloat16 g_Zb2[NB * KB2];
__device__ __nv_bfloat16 g_Wb1[GDIM * KB1];   // permuted rows jp = unit*4+gate
__device__ __nv_bfloat16 g_Wb2[GDIM * KB2];
__device__ float g_biasP[GDIM];
__device__ float g_C[NB * NF];                // LSTM cell state
__device__ float g_Gp[NSPLIT * NB * GDIM];    // split-K partials
__device__ int   g_seg[NB + 2];

// ---------------- helpers ----------------------------------------------------
__device__ __forceinline__ uint32_t smem_u32(const void* p) {
    return (uint32_t)__cvta_generic_to_shared(p);
}
__device__ __forceinline__ float sigmoidf_(float x) { return 1.0f / (1.0f + expf(-x)); }

__device__ __forceinline__ void cp16(uint32_t dst, const void* src) {
    asm volatile("cp.async.cg.shared.global [%0], [%1], 16;" :: "r"(dst), "l"(src) : "memory");
}
#define CP_COMMIT() asm volatile("cp.async.commit_group;" ::: "memory")

// x loads: keep resident in L2 across passes (cache-hint policy form)
__device__ __forceinline__ uint64_t mk_policy() {
    uint64_t pol;
    asm volatile("createpolicy.fractional.L2::evict_last.b64 %0, 1.0;" : "=l"(pol));
    return pol;
}
__device__ __forceinline__ float4 ld_el(const float* p, uint64_t pol) {
    float4 v;
    asm volatile("ld.global.nc.L2::cache_hint.v4.f32 {%0,%1,%2,%3}, [%4], %5;"
                 : "=f"(v.x), "=f"(v.y), "=f"(v.z), "=f"(v.w) : "l"(p), "l"(pol));
    return v;
}

__device__ __forceinline__ void mma_bf16(float d[4], const uint32_t a[4], const uint32_t b[2]) {
    asm volatile(
        "mma.sync.aligned.m16n8k16.row.col.f32.bf16.bf16.f32 "
        "{%0,%1,%2,%3}, {%4,%5,%6,%7}, {%8,%9}, {%0,%1,%2,%3};\n"
        : "+f"(d[0]), "+f"(d[1]), "+f"(d[2]), "+f"(d[3])
        : "r"(a[0]), "r"(a[1]), "r"(a[2]), "r"(a[3]), "r"(b[0]), "r"(b[1]));
}

// ---------------- merged setup: weights, bias, bounds, Z init -----------------
__global__ void k_setup(const float* __restrict__ W_ih, const float* __restrict__ W_hh,
                        const float* __restrict__ b_ih, const float* __restrict__ b_hh,
                        const int* __restrict__ batch, const float* __restrict__ qstar,
                        int n) {
    int idx = blockIdx.x * blockDim.x + threadIdx.x;
    const int RW1 = GDIM * KB1;
    const int RW2 = RW1 + GDIM * KB2;
    const int RB  = RW2 + GDIM;
    const int RS  = RB + n;
    const int RZ1 = RS + NB * KB1;
    const int RC  = RZ1 + NB * NF;
    const int RZ2 = RC + NB * 144;
    if (idx < RW1) {
        int jp = idx / KB1, u = idx % KB1;
        int j = (jp & 3) * 200 + (jp >> 2);
        int s = u / SEC1, k = u % SEC1;
        float a = 0.f;
        if (k < 400)      a = W_ih[j * 400 + k];
        else if (k < 600) a = W_hh[j * 200 + (k - 400)];
        __nv_bfloat16 hi = __float2bfloat16(a);
        g_Wb1[idx] = (s < 2) ? hi : __float2bfloat16(a - __bfloat162float(hi));
    } else if (idx < RW2) {
        int t = idx - RW1;
        int jp = t / KB2, u = t % KB2;
        int j = (jp & 3) * 200 + (jp >> 2);
        int s = u / SEC2, k = u % SEC2;
        float a = 0.f;
        if (k < 400) {
            a = W_ih[j * 400 + k];
            if (k < 200) a += W_hh[j * 200 + k];
        }
        __nv_bfloat16 hi = __float2bfloat16(a);
        g_Wb2[t] = (s < 2) ? hi : __float2bfloat16(a - __bfloat162float(hi));
    } else if (idx < RB) {
        int jp = idx - RW2;
        int j = (jp & 3) * 200 + (jp >> 2);
        g_biasP[jp] = b_ih[j] + b_hh[j];
    } else if (idx < RS) {
        int i = idx - RB;
        int b = batch[i];
        if (i == 0) { for (int q = 0; q <= b; ++q) g_seg[q] = 0; }
        else {
            int pb = batch[i - 1];
            for (int q = pb + 1; q <= b; ++q) g_seg[q] = i;
        }
        if (i == n - 1) { for (int q = b + 1; q <= NB; ++q) g_seg[q] = n; }
    } else if (idx < RZ1) {
        int t = idx - RS;
        int b = t / KB1, u = t % KB1;
        int s = u / SEC1, k = u % SEC1;
        if (k < 400) {
            float v = qstar[b * 400 + k];
            __nv_bfloat16 hi = __float2bfloat16(v);
            g_Zb1[t] = (s == 1) ? __float2bfloat16(v - __bfloat162float(hi)) : hi;
        } else if (k >= 600) {
            g_Zb1[t] = __float2bfloat16(0.f);
        }
    } else if (idx < RC) {
        g_C[idx - RZ1] = 0.f;
    } else if (idx < RZ2) {
        int t = idx - RC;
        int b = t / 144, k = t % 144;
        int sec = k / 48;
        g_Zb2[b * KB2 + sec * SEC2 + 400 + (k % 48)] = __float2bfloat16(0.f);
    }
}

// ---------------- h0 = segment_sum(cos*x) → Zb1 h sections --------------------
__global__ void __launch_bounds__(256) k_h0(const float* __restrict__ x,
                                            const float* __restrict__ cosc) {
    __shared__ float part[8][NF];
    int b = blockIdx.x;
    int s0 = g_seg[b], s1 = g_seg[b + 1];
    int tid = threadIdx.x, lane = tid & 31, wid = tid >> 5;
    uint64_t pol = mk_policy();

    float4 aA = make_float4(0.f, 0.f, 0.f, 0.f);
    float4 aB = make_float4(0.f, 0.f, 0.f, 0.f);
    for (int n = s0 + wid; n < s1; n += 8) {
        float c = __ldg(cosc + n);
        const float* rp = x + (size_t)n * NF;
        float4 v = ld_el(rp + 4 * lane, pol);
        aA.x += c * v.x; aA.y += c * v.y; aA.z += c * v.z; aA.w += c * v.w;
        if (lane < 18) {
            float4 v2 = ld_el(rp + 128 + 4 * lane, pol);
            aB.x += c * v2.x; aB.y += c * v2.y; aB.z += c * v2.z; aB.w += c * v2.w;
        }
    }
    part[wid][4 * lane + 0] = aA.x; part[wid][4 * lane + 1] = aA.y;
    part[wid][4 * lane + 2] = aA.z; part[wid][4 * lane + 3] = aA.w;
    if (lane < 18) {
        part[wid][128 + 4 * lane + 0] = aB.x; part[wid][128 + 4 * lane + 1] = aB.y;
        part[wid][128 + 4 * lane + 2] = aB.z; part[wid][128 + 4 * lane + 3] = aB.w;
    }
    __syncthreads();
    if (tid < NF) {
        float s = 0.f;
#pragma unroll
        for (int w = 0; w < 8; ++w) s += part[w][tid];
        __nv_bfloat16 hi = __float2bfloat16(s);
        __nv_bfloat16 lo = __float2bfloat16(s - __bfloat162float(hi));
        size_t base = (size_t)b * KB1;
        g_Zb1[base + 400 + tid] = hi;
        g_Zb1[base + SEC1 + 400 + tid] = lo;
        g_Zb1[base + 2 * SEC1 + 400 + tid] = hi;
    }
}

// -------- split-K mma.sync bf16 GEMM (CTA 128x80, 3 K-splits, 2 stages) --------
template<int KB, int NCHUNK>
__global__ void __launch_bounds__(256, 3) k_gemm_split(const __nv_bfloat16* __restrict__ A,
                                                       const __nv_bfloat16* __restrict__ Wb) {
    extern __shared__ char smem[];
    uint32_t sbase = smem_u32(smem);
    int tid = threadIdx.x, lane = tid & 31, warp = tid >> 5;
    int m0 = blockIdx.x * GM;
    int n0 = blockIdx.y * GNT;
    int z  = blockIdx.z;
    int c0 = (z * NCHUNK) / NSPLIT, c1 = ((z + 1) * NCHUNK) / NSPLIT;

    int wm = warp >> 1, wn = warp & 1;
    int r7 = lane & 7, quad = lane >> 3;
    int gg = lane >> 2, t4 = lane & 3;

    float acc[2][5][4];
#pragma unroll
    for (int t = 0; t < 2; ++t)
#pragma unroll
        for (int u = 0; u < 5; ++u)
#pragma unroll
            for (int v = 0; v < 4; ++v) acc[t][u][v] = 0.f;

    auto load_chunk = [&](int c) {
        int s = (c - c0) % NSTAGE;
        uint32_t aBase = sbase + SOFF + s * STG;
        uint32_t bBase = aBase + 16384;
        const __nv_bfloat16* gA = A + (size_t)m0 * KB + c * 64;
        const __nv_bfloat16* gW = Wb + (size_t)n0 * KB + c * 64;
#pragma unroll
        for (int i = 0; i < 4; ++i) {
            int t = tid + i * 256;
            int r = t >> 3, v = t & 7;
            uint32_t bo = (uint32_t)r * 128 + v * 16;
            cp16(aBase + (bo ^ ((r & 7) << 4)), gA + (size_t)r * KB + v * 8);
        }
        for (int t = tid; t < 80 * 8; t += 256) {
            int r = t >> 3, v = t & 7;
            uint32_t bo = (uint32_t)r * 128 + v * 16;
            cp16(bBase + (bo ^ ((r & 7) << 4)), gW + (size_t)r * KB + v * 8);
        }
        CP_COMMIT();
    };

    auto compute = [&](int slot) {
        uint32_t aB = sbase + SOFF + slot * STG;
        uint32_t bB = aB + 16384;
#pragma unroll
        for (int k16 = 0; k16 < 4; ++k16) {
            int kb = k16 * 32;
            uint32_t aF[2][4], bF[5][2];
#pragma unroll
            for (int t = 0; t < 2; ++t) {
                int row = wm * 32 + t * 16 + (quad & 1) * 8 + r7;
                int cb = kb + (quad >> 1) * 16;
                uint32_t ad = aB + (((uint32_t)row * 128 + cb) ^ ((row & 7) << 4));
                asm volatile("ldmatrix.sync.aligned.m8n8.x4.shared.b16 {%0,%1,%2,%3}, [%4];"
                             : "=r"(aF[t][0]), "=r"(aF[t][1]), "=r"(aF[t][2]), "=r"(aF[t][3])
                             : "r"(ad));
            }
#pragma unroll
            for (int p = 0; p < 2; ++p) {
                int row = wn * 40 + (2 * p + (quad >> 1)) * 8 + r7;
                int cb = kb + (quad & 1) * 16;
                uint32_t bd = bB + (((uint32_t)row * 128 + cb) ^ ((row & 7) << 4));
                asm volatile("ldmatrix.sync.aligned.m8n8.x4.shared.b16 {%0,%1,%2,%3}, [%4];"
                             : "=r"(bF[2 * p][0]), "=r"(bF[2 * p][1]),
                               "=r"(bF[2 * p + 1][0]), "=r"(bF[2 * p + 1][1])
                             : "r"(bd));
            }
            {
                int row = wn * 40 + 32 + r7;
                int cb = kb + (quad & 1) * 16;
                uint32_t bd = bB + (((uint32_t)row * 128 + cb) ^ ((row & 7) << 4));
                asm volatile("ldmatrix.sync.aligned.m8n8.x2.shared.b16 {%0,%1}, [%2];"
                             : "=r"(bF[4][0]), "=r"(bF[4][1]) : "r"(bd));
            }
#pragma unroll
            for (int t = 0; t < 2; ++t)
#pragma unroll
                for (int u = 0; u < 5; ++u) mma_bf16(acc[t][u], aF[t], bF[u]);
        }
    };

    load_chunk(c0);
    if (c0 + 1 < c1) load_chunk(c0 + 1);
    for (int c = c0; c < c1; ++c) {
        if (c + 1 < c1) asm volatile("cp.async.wait_group 1;" ::: "memory");
        else            asm volatile("cp.async.wait_group 0;" ::: "memory");
        __syncthreads();
        compute((c - c0) % NSTAGE);
        if (c + 2 < c1) {
            __syncthreads();              // stage free before overwrite
            load_chunk(c + 2);
        }
    }

    // write partials
    float* Gp = g_Gp + (size_t)z * NB * GDIM;
#pragma unroll
    for (int t = 0; t < 2; ++t)
#pragma unroll
        for (int u = 0; u < 5; ++u) {
            int row = m0 + wm * 32 + t * 16 + gg;
            int col = n0 + wn * 40 + u * 8 + 2 * t4;
            *(float2*)(Gp + (size_t)row * GDIM + col)       = make_float2(acc[t][u][0], acc[t][u][1]);
            *(float2*)(Gp + (size_t)(row + 8) * GDIM + col) = make_float2(acc[t][u][2], acc[t][u][3]);
        }
}

// --- fused: split-K reduce + LSTM pointwise (prologue) + online-softmax attn ---
__global__ void __launch_bounds__(256, 5) k_attn(const float* __restrict__ x,
                                                 float* __restrict__ out, int writeOut) {
    __shared__ float qs[208];
    __shared__ float part[8][NF];
    __shared__ float pm[8], ps[8], fac[8];

    int b = blockIdx.x;
    int s0 = g_seg[b], s1 = g_seg[b + 1];
    int tid = threadIdx.x, lane = tid & 31, wid = tid >> 5;
    uint64_t pol = mk_policy();

    // ---- prologue: sum 3 split-K partials, LSTM pointwise → q (row b) --------
    if (tid < NF) {
        const float* p0 = g_Gp + (size_t)b * GDIM + 4 * tid;
        float4 s = *(const float4*)p0;
#pragma unroll
        for (int z = 1; z < NSPLIT; ++z) {
            float4 t = *(const float4*)(p0 + (size_t)z * NB * GDIM);
            s.x += t.x; s.y += t.y; s.z += t.z; s.w += t.w;
        }
        const float4 bb = *(const float4*)(g_biasP + 4 * tid);
        float i_ = s.x + bb.x;
        float f_ = s.y + bb.y;
        float g_ = s.z + bb.z;
        float o_ = s.w + bb.w;
        float c = g_C[(size_t)b * NF + tid];
        c = sigmoidf_(f_) * c + sigmoidf_(i_) * tanhf(g_);
        float h = sigmoidf_(o_) * tanhf(c);
        g_C[(size_t)b * NF + tid] = c;
        qs[tid] = h;
        __nv_bfloat16 hi = __float2bfloat16(h);
        __nv_bfloat16 lo = __float2bfloat16(h - __bfloat162float(hi));
        __nv_bfloat16* Zr = g_Zb2 + (size_t)b * KB2;
        Zr[tid] = hi; Zr[SEC2 + tid] = lo; Zr[2 * SEC2 + tid] = hi;
    }
    __syncthreads();

    const float4* q4 = (const float4*)qs;
    float4 qa = q4[lane];
    float4 qb = make_float4(0.f, 0.f, 0.f, 0.f);
    if (lane < 18) qb = q4[32 + lane];

    float4 ra = make_float4(0.f, 0.f, 0.f, 0.f);
    float4 rb = make_float4(0.f, 0.f, 0.f, 0.f);
    float run_m = -3.0e38f, run_s = 0.f;

    for (int n = s0 + wid; n < s1; n += 8) {
        const float* rp = x + (size_t)n * NF;
        float4 va = ld_el(rp + 4 * lane, pol);
        float4 vb = make_float4(0.f, 0.f, 0.f, 0.f);
        float p = va.x * qa.x + va.y * qa.y + va.z * qa.z + va.w * qa.w;
        if (lane < 18) {
            vb = ld_el(rp + 128 + 4 * lane, pol);
            p += vb.x * qb.x + vb.y * qb.y + vb.z * qb.z + vb.w * qb.w;
        }
#pragma unroll
        for (int o = 16; o > 0; o >>= 1) p += __shfl_xor_sync(0xffffffffu, p, o);
        if (p > run_m) {
            float sc = __expf(run_m - p);
            ra.x *= sc; ra.y *= sc; ra.z *= sc; ra.w *= sc;
            rb.x *= sc; rb.y *= sc; rb.z *= sc; rb.w *= sc;
            run_s *= sc;
            run_m = p;
        }
        float w = __expf(p - run_m);
        run_s += w;
        ra.x += w * va.x; ra.y += w * va.y; ra.z += w * va.z; ra.w += w * va.w;
        rb.x += w * vb.x; rb.y += w * vb.y; rb.z += w * vb.z; rb.w += w * vb.w;
    }

    part[wid][4 * lane + 0] = ra.x; part[wid][4 * lane + 1] = ra.y;
    part[wid][4 * lane + 2] = ra.z; part[wid][4 * lane + 3] = ra.w;
    if (lane < 18) {
        part[wid][128 + 4 * lane + 0] = rb.x; part[wid][128 + 4 * lane + 1] = rb.y;
        part[wid][128 + 4 * lane + 2] = rb.z; part[wid][128 + 4 * lane + 3] = rb.w;
    }
    if (lane == 0) { pm[wid] = run_m; ps[wid] = run_s; }
    __syncthreads();

    if (tid < 8) {
        float M = pm[0];
#pragma unroll
        for (int w = 1; w < 8; ++w) M = fmaxf(M, pm[w]);
        fac[tid] = __expf(pm[tid] - M);
    }
    __syncthreads();

    if (tid < NF) {
        float denom = 0.f, r = 0.f;
#pragma unroll
        for (int w = 0; w < 8; ++w) {
            denom += fac[w] * ps[w];
            r     += fac[w] * part[w][tid];
        }
        r = (denom > 0.f) ? (r / denom) : 0.f;
        __nv_bfloat16 hi = __float2bfloat16(r);
        __nv_bfloat16 lo = __float2bfloat16(r - __bfloat162float(hi));
        size_t base = (size_t)b * KB2 + 200 + tid;
        g_Zb2[base] = hi;
        g_Zb2[base + SEC2] = lo;
        g_Zb2[base + 2 * SEC2] = hi;
        if (writeOut) {
            out[b * 400 + tid] = qs[tid];
            out[b * 400 + 200 + tid] = r;
        }
    }
}

// ---------------- launch ---------------------------------------------------------
extern "C" void kernel_launch(void* const* d_in, const int* in_sizes, int n_in,
                              void* d_out, int out_size) {
    const float* x     = (const float*)d_in[0];
    const int*   batch = (const int*)  d_in[1];
    const float* cosc  = (const float*)d_in[2];
    const float* qstar = (const float*)d_in[3];
    const float* W_ih  = (const float*)d_in[4];
    const float* W_hh  = (const float*)d_in[5];
    const float* b_ih  = (const float*)d_in[6];
    const float* b_hh  = (const float*)d_in[7];
    float* out = (float*)d_out;

    int n = in_sizes[1];

    const int smemBytes = SOFF + NSTAGE * STG;   // 54272
    cudaFuncSetAttribute(k_gemm_split<KB1, NCH1>,
                         cudaFuncAttributeMaxDynamicSharedMemorySize, smemBytes);
    cudaFuncSetAttribute(k_gemm_split<KB2, NCH2>,
                         cudaFuncAttributeMaxDynamicSharedMemorySize, smemBytes);

    __nv_bfloat16 *zb1, *zb2, *wb1, *wb2;
    cudaGetSymbolAddress((void**)&zb1, g_Zb1);
    cudaGetSymbolAddress((void**)&zb2, g_Zb2);
    cudaGetSymbolAddress((void**)&wb1, g_Wb1);
    cudaGetSymbolAddress((void**)&wb2, g_Wb2);

    const int setupTot = GDIM * KB1 + GDIM * KB2 + GDIM + n + NB * KB1 + NB * NF + NB * 144;
    k_setup<<<(setupTot + 255) / 256, 256>>>(W_ih, W_hh, b_ih, b_hh, batch, qstar, n);
    k_h0   <<<NB, 256>>>(x, cosc);

    dim3 ggrid(NB / GM, GDIM / GNT, NSPLIT);     // 16 x 10 x 3 = 480 CTAs
    for (int s = 0; s < STEPS; ++s) {
        if (s == 0) k_gemm_split<KB1, NCH1><<<ggrid, 256, smemBytes>>>(zb1, wb1);
        else        k_gemm_split<KB2, NCH2><<<ggrid, 256, smemBytes>>>(zb2, wb2);
        k_attn<<<NB, 256>>>(x, out, s == STEPS - 1 ? 1 : 0);
    }
}